// round 2
// baseline (speedup 1.0000x reference)
#include <cuda_runtime.h>
#include <math.h>

#define BB  16
#define NPT 1024
#define EPSW 1e-5f
#define L2E 1.4426950408889634f
#define LN2 0.6931471805599453f

// ---------------- scratch (static device globals; no allocations) ----------------
static __device__ float  g_refSoA[BB][6][NPT];   // ref features, SoA
static __device__ float  g_gn[BB][NPT];          // |g_k|^2
static __device__ float  g_featS[BB][6][NPT];    // transformed src features, SoA
static __device__ float  g_fn[BB][NPT];          // |f_j|^2
static __device__ float  g_u[BB][NPT];
static __device__ float  g_v[BB][NPT];
static __device__ float  g_w[BB][NPT];           // row weights (sum_k perm)
static __device__ float  g_wrx[BB][NPT];
static __device__ float  g_wry[BB][NPT];
static __device__ float  g_wrz[BB][NPT];
static __device__ double g_T[BB][12];            // accumulated transform, row-major 3x4

__device__ __forceinline__ float fast_ex2(float x){ float y; asm("ex2.approx.ftz.f32 %0, %1;" : "=f"(y) : "f"(x)); return y; }
__device__ __forceinline__ float fast_lg2(float x){ float y; asm("lg2.approx.f32 %0, %1;" : "=f"(y) : "f"(x)); return y; }
__device__ __forceinline__ int dval(const int* p, int d){ return p ? __ldg(p) : d; }

// ---------------- init: ref -> SoA, |g|^2, transform = I ----------------
__global__ void k_init(const float* __restrict__ ref)
{
    int idx = blockIdx.x * 256 + threadIdx.x;
    if (idx < BB * NPT) {
        int b = idx >> 10, k = idx & 1023;
        const float* p = ref + (size_t)idx * 6;
        float n = 0.f;
#pragma unroll
        for (int c = 0; c < 6; c++) { float x = p[c]; g_refSoA[b][c][k] = x; n += x * x; }
        g_gn[b][k] = n;
    }
    if (idx < BB) {
        double* T = g_T[idx];
#pragma unroll
        for (int m = 0; m < 3; m++)
#pragma unroll
            for (int c = 0; c < 4; c++) T[m * 4 + c] = (m == c) ? 1.0 : 0.0;
    }
}

// ---------------- prep: src_t = R*src + t, features SoA, zero v ----------------
__global__ void k_prep(const int* nreg, int r, const float* __restrict__ src)
{
    if (r >= dval(nreg, 3)) return;
    int idx = blockIdx.x * 256 + threadIdx.x;
    if (idx >= BB * NPT) return;
    int b = idx >> 10, j = idx & 1023;
    const double* T = g_T[b];
    const float* p = src + (size_t)idx * 6;
    float x = p[0], y = p[1], z = p[2], n3 = p[3], n4 = p[4], n5 = p[5];
    float q0 = (float)(T[0] * x + T[1] * y + T[2]  * z + T[3]);
    float q1 = (float)(T[4] * x + T[5] * y + T[6]  * z + T[7]);
    float q2 = (float)(T[8] * x + T[9] * y + T[10] * z + T[11]);
    g_featS[b][0][j] = q0; g_featS[b][1][j] = q1; g_featS[b][2][j] = q2;
    g_featS[b][3][j] = n3; g_featS[b][4][j] = n4; g_featS[b][5][j] = n5;
    g_fn[b][j] = q0*q0 + q1*q1 + q2*q2 + n3*n3 + n4*n4 + n5*n5;
    g_v[b][j] = 0.f;
}

// ---------------- Sinkhorn row pass: u_j = log(1 + sum_k exp(a - v_k)) ----------------
__global__ void __launch_bounds__(256) k_row(const int* nreg, const int* nsk, int r, int s,
                                             const float* __restrict__ beta_, const float* __restrict__ alpha_)
{
    if (r >= dval(nreg, 3) || s >= dval(nsk, 5)) return;
    int b = blockIdx.y;
    __shared__ float gs[6][NPT];
    __shared__ float pk[NPT];
    float bet = beta_[b];
    float bl  = bet * L2E;
    for (int i = threadIdx.x; i < NPT; i += 256) {
#pragma unroll
        for (int c = 0; c < 6; c++) gs[c][i] = g_refSoA[b][c][i];
        pk[i] = bl * g_gn[b][i] + L2E * g_v[b][i];
    }
    __syncthreads();
    int warp = threadIdx.x >> 5, lane = threadIdx.x & 31;
    int j0 = blockIdx.x * 32 + warp * 4;
    float al = alpha_[b];
    float wj[4][6], cj[4];
#pragma unroll
    for (int t = 0; t < 4; t++) {
        int j = j0 + t;
#pragma unroll
        for (int c = 0; c < 6; c++) wj[t][c] = 2.f * bl * g_featS[b][c][j];
        cj[t] = bl * (al - g_fn[b][j]);
    }
    float acc[4] = {0.f, 0.f, 0.f, 0.f};
#pragma unroll 2
    for (int i = 0; i < 32; i++) {
        int k = i * 32 + lane;
        float G[6];
#pragma unroll
        for (int c = 0; c < 6; c++) G[c] = gs[c][k];
        float P = pk[k];
#pragma unroll
        for (int t = 0; t < 4; t++) {
            float a = cj[t] - P;
#pragma unroll
            for (int c = 0; c < 6; c++) a = fmaf(wj[t][c], G[c], a);
            acc[t] += fast_ex2(a);
        }
    }
#pragma unroll
    for (int t = 0; t < 4; t++)
#pragma unroll
        for (int o = 16; o; o >>= 1) acc[t] += __shfl_xor_sync(0xffffffffu, acc[t], o);
    if (lane == 0) {
        g_u[b][j0 + 0] = LN2 * fast_lg2(1.f + acc[0]);
        g_u[b][j0 + 1] = LN2 * fast_lg2(1.f + acc[1]);
        g_u[b][j0 + 2] = LN2 * fast_lg2(1.f + acc[2]);
        g_u[b][j0 + 3] = LN2 * fast_lg2(1.f + acc[3]);
    }
}

// ---------------- Sinkhorn col pass: v_k = log(1 + sum_j exp(a - u_j)) ----------------
__global__ void __launch_bounds__(256) k_col(const int* nreg, const int* nsk, int r, int s,
                                             const float* __restrict__ beta_, const float* __restrict__ alpha_)
{
    if (r >= dval(nreg, 3) || s >= dval(nsk, 5)) return;
    int b = blockIdx.y;
    __shared__ float fs[6][NPT];
    __shared__ float qj[NPT];
    float bet = beta_[b];
    float bl  = bet * L2E;
    for (int i = threadIdx.x; i < NPT; i += 256) {
#pragma unroll
        for (int c = 0; c < 6; c++) fs[c][i] = g_featS[b][c][i];
        qj[i] = bl * g_fn[b][i] + L2E * g_u[b][i];
    }
    __syncthreads();
    int warp = threadIdx.x >> 5, lane = threadIdx.x & 31;
    int k0 = blockIdx.x * 32 + warp * 4;
    float al = alpha_[b];
    float wk[4][6], ck[4];
#pragma unroll
    for (int t = 0; t < 4; t++) {
        int k = k0 + t;
#pragma unroll
        for (int c = 0; c < 6; c++) wk[t][c] = 2.f * bl * g_refSoA[b][c][k];
        ck[t] = bl * (al - g_gn[b][k]);
    }
    float acc[4] = {0.f, 0.f, 0.f, 0.f};
#pragma unroll 2
    for (int i = 0; i < 32; i++) {
        int j = i * 32 + lane;
        float F[6];
#pragma unroll
        for (int c = 0; c < 6; c++) F[c] = fs[c][j];
        float Q = qj[j];
#pragma unroll
        for (int t = 0; t < 4; t++) {
            float a = ck[t] - Q;
#pragma unroll
            for (int c = 0; c < 6; c++) a = fmaf(wk[t][c], F[c], a);
            acc[t] += fast_ex2(a);
        }
    }
#pragma unroll
    for (int t = 0; t < 4; t++)
#pragma unroll
        for (int o = 16; o; o >>= 1) acc[t] += __shfl_xor_sync(0xffffffffu, acc[t], o);
    if (lane == 0) {
        g_v[b][k0 + 0] = LN2 * fast_lg2(1.f + acc[0]);
        g_v[b][k0 + 1] = LN2 * fast_lg2(1.f + acc[1]);
        g_v[b][k0 + 2] = LN2 * fast_lg2(1.f + acc[2]);
        g_v[b][k0 + 3] = LN2 * fast_lg2(1.f + acc[3]);
    }
}

// ---------------- consume: row sums, perm @ ref_xyz, (last iter) write perm ----------------
__global__ void __launch_bounds__(256) k_consume(const int* nreg, int r,
                                                 const float* __restrict__ beta_, const float* __restrict__ alpha_,
                                                 float* __restrict__ perm_out)
{
    int nr = dval(nreg, 3);
    if (r >= nr) return;
    bool last = (r == nr - 1);
    int b = blockIdx.y;
    __shared__ float gs[6][NPT];
    __shared__ float pk[NPT];
    float bet = beta_[b];
    float bl  = bet * L2E;
    for (int i = threadIdx.x; i < NPT; i += 256) {
#pragma unroll
        for (int c = 0; c < 6; c++) gs[c][i] = g_refSoA[b][c][i];
        pk[i] = bl * g_gn[b][i] + L2E * g_v[b][i];
    }
    __syncthreads();
    int warp = threadIdx.x >> 5, lane = threadIdx.x & 31;
    int j0 = blockIdx.x * 32 + warp * 4;
    float al = alpha_[b];
    float wj[4][6], cj[4], eu[4];
#pragma unroll
    for (int t = 0; t < 4; t++) {
        int j = j0 + t;
#pragma unroll
        for (int c = 0; c < 6; c++) wj[t][c] = 2.f * bl * g_featS[b][c][j];
        cj[t] = bl * (al - g_fn[b][j]);
        eu[t] = fast_ex2(-L2E * g_u[b][j]);   // exp(-u_j)
    }
    float S[4] = {0,0,0,0}, SX[4] = {0,0,0,0}, SY[4] = {0,0,0,0}, SZ[4] = {0,0,0,0};
    if (last) {
        float* pb[4];
#pragma unroll
        for (int t = 0; t < 4; t++) pb[t] = perm_out + ((size_t)(b * NPT + j0 + t)) * NPT;
#pragma unroll 2
        for (int i = 0; i < 32; i++) {
            int k = i * 32 + lane;
            float G[6];
#pragma unroll
            for (int c = 0; c < 6; c++) G[c] = gs[c][k];
            float P = pk[k];
#pragma unroll
            for (int t = 0; t < 4; t++) {
                float a = cj[t] - P;
#pragma unroll
                for (int c = 0; c < 6; c++) a = fmaf(wj[t][c], G[c], a);
                float e = fast_ex2(a);
                S[t] += e;
                SX[t] = fmaf(e, G[0], SX[t]);
                SY[t] = fmaf(e, G[1], SY[t]);
                SZ[t] = fmaf(e, G[2], SZ[t]);
                pb[t][k] = e * eu[t];
            }
        }
    } else {
#pragma unroll 2
        for (int i = 0; i < 32; i++) {
            int k = i * 32 + lane;
            float G[6];
#pragma unroll
            for (int c = 0; c < 6; c++) G[c] = gs[c][k];
            float P = pk[k];
#pragma unroll
            for (int t = 0; t < 4; t++) {
                float a = cj[t] - P;
#pragma unroll
                for (int c = 0; c < 6; c++) a = fmaf(wj[t][c], G[c], a);
                float e = fast_ex2(a);
                S[t] += e;
                SX[t] = fmaf(e, G[0], SX[t]);
                SY[t] = fmaf(e, G[1], SY[t]);
                SZ[t] = fmaf(e, G[2], SZ[t]);
            }
        }
    }
#pragma unroll
    for (int t = 0; t < 4; t++) {
#pragma unroll
        for (int o = 16; o; o >>= 1) {
            S[t]  += __shfl_xor_sync(0xffffffffu, S[t],  o);
            SX[t] += __shfl_xor_sync(0xffffffffu, SX[t], o);
            SY[t] += __shfl_xor_sync(0xffffffffu, SY[t], o);
            SZ[t] += __shfl_xor_sync(0xffffffffu, SZ[t], o);
        }
    }
    if (lane == 0) {
#pragma unroll
        for (int t = 0; t < 4; t++) {
            int j = j0 + t;
            float W = S[t] * eu[t];
            g_w[b][j] = W;
            float inv = 1.f / (W + EPSW);
            g_wrx[b][j] = SX[t] * eu[t] * inv;
            g_wry[b][j] = SY[t] * eu[t] * inv;
            g_wrz[b][j] = SZ[t] * eu[t] * inv;
        }
    }
}

// ---------------- fit: weighted Kabsch (fp64 Jacobi SVD) + compose transform ----------------
__global__ void __launch_bounds__(256) k_fit(const int* nreg, int r, float* __restrict__ T_out)
{
    int nr = dval(nreg, 3);
    if (r >= nr) return;
    int b = blockIdx.x;
    int lane = threadIdx.x & 31, warp = threadIdx.x >> 5;
    __shared__ double sred[8][9];
    __shared__ double sc[8];

    // phase 1: W, sum w*a, sum w*b
    double acc[7] = {0,0,0,0,0,0,0};
    for (int j = threadIdx.x; j < NPT; j += 256) {
        double w  = g_w[b][j];
        double ax = g_featS[b][0][j], ay = g_featS[b][1][j], az = g_featS[b][2][j];
        double bx = g_wrx[b][j], by = g_wry[b][j], bz = g_wrz[b][j];
        acc[0] += w;
        acc[1] += w*ax; acc[2] += w*ay; acc[3] += w*az;
        acc[4] += w*bx; acc[5] += w*by; acc[6] += w*bz;
    }
#pragma unroll
    for (int i = 0; i < 7; i++)
#pragma unroll
        for (int o = 16; o; o >>= 1) acc[i] += __shfl_xor_sync(0xffffffffu, acc[i], o);
    if (lane == 0)
#pragma unroll
        for (int i = 0; i < 7; i++) sred[warp][i] = acc[i];
    __syncthreads();
    if (threadIdx.x == 0) {
        double tot[7] = {0,0,0,0,0,0,0};
        for (int w = 0; w < 8; w++)
            for (int i = 0; i < 7; i++) tot[i] += sred[w][i];
        double den = tot[0] + 1e-5;
        sc[0] = den;
        for (int i = 0; i < 6; i++) sc[1 + i] = tot[1 + i] / den;
    }
    __syncthreads();
    double den = sc[0];
    double ca0 = sc[1], ca1 = sc[2], ca2 = sc[3];
    double cb0 = sc[4], cb1 = sc[5], cb2 = sc[6];

    // phase 2: cov = sum wn (a-ca)(b-cb)^T
    double cv[9] = {0,0,0,0,0,0,0,0,0};
    for (int j = threadIdx.x; j < NPT; j += 256) {
        double wn = (double)g_w[b][j] / den;
        double ax = g_featS[b][0][j] - ca0, ay = g_featS[b][1][j] - ca1, az = g_featS[b][2][j] - ca2;
        double bx = g_wrx[b][j] - cb0, by = g_wry[b][j] - cb1, bz = g_wrz[b][j] - cb2;
        cv[0] += wn*ax*bx; cv[1] += wn*ax*by; cv[2] += wn*ax*bz;
        cv[3] += wn*ay*bx; cv[4] += wn*ay*by; cv[5] += wn*ay*bz;
        cv[6] += wn*az*bx; cv[7] += wn*az*by; cv[8] += wn*az*bz;
    }
#pragma unroll
    for (int i = 0; i < 9; i++)
#pragma unroll
        for (int o = 16; o; o >>= 1) cv[i] += __shfl_xor_sync(0xffffffffu, cv[i], o);
    if (lane == 0)
#pragma unroll
        for (int i = 0; i < 9; i++) sred[warp][i] = cv[i];
    __syncthreads();

    if (threadIdx.x == 0) {
        double C[3][3];
        {
            double tot[9] = {0,0,0,0,0,0,0,0,0};
            for (int w = 0; w < 8; w++)
                for (int i = 0; i < 9; i++) tot[i] += sred[w][i];
            for (int m = 0; m < 3; m++)
                for (int n = 0; n < 3; n++) C[m][n] = tot[m * 3 + n];
        }
        // A = C^T C, Jacobi eigendecomposition -> V
        double A[3][3];
        for (int i = 0; i < 3; i++)
            for (int j = 0; j < 3; j++)
                A[i][j] = C[0][i]*C[0][j] + C[1][i]*C[1][j] + C[2][i]*C[2][j];
        double V[3][3] = {{1,0,0},{0,1,0},{0,0,1}};
        const int PP[3] = {0,0,1}, QQ[3] = {1,2,2};
        for (int sweep = 0; sweep < 30; sweep++) {
            double off = A[0][1]*A[0][1] + A[0][2]*A[0][2] + A[1][2]*A[1][2];
            if (off < 1e-26) break;
            for (int pi = 0; pi < 3; pi++) {
                int p = PP[pi], q = QQ[pi];
                double apq = A[p][q];
                if (fabs(apq) < 1e-300) continue;
                double theta = (A[q][q] - A[p][p]) / (2.0 * apq);
                double tt = ((theta >= 0.0) ? 1.0 : -1.0) / (fabs(theta) + sqrt(theta*theta + 1.0));
                double c = 1.0 / sqrt(tt*tt + 1.0), sn = tt * c;
                int m = 3 - p - q;
                double amp = A[m][p], amq = A[m][q];
                double app = A[p][p], aqq = A[q][q];
                A[p][p] = app - tt * apq;
                A[q][q] = aqq + tt * apq;
                A[p][q] = A[q][p] = 0.0;
                A[m][p] = A[p][m] = c*amp - sn*amq;
                A[m][q] = A[q][m] = sn*amp + c*amq;
                for (int mm = 0; mm < 3; mm++) {
                    double vp = V[mm][p], vq = V[mm][q];
                    V[mm][p] = c*vp - sn*vq;
                    V[mm][q] = sn*vp + c*vq;
                }
            }
        }
        double lam[3] = {A[0][0], A[1][1], A[2][2]};
        // sort eigenpairs descending (columns of V)
        for (int i = 0; i < 2; i++)
            for (int j = i + 1; j < 3; j++)
                if (lam[j] > lam[i]) {
                    double tl = lam[i]; lam[i] = lam[j]; lam[j] = tl;
                    for (int m = 0; m < 3; m++) { double tv = V[m][i]; V[m][i] = V[m][j]; V[m][j] = tv; }
                }
        double v0[3] = {V[0][0], V[1][0], V[2][0]};
        double v1[3] = {V[0][1], V[1][1], V[2][1]};
        double v2[3] = {V[0][2], V[1][2], V[2][2]};
        double u0[3], u1[3], u2[3];
        for (int m = 0; m < 3; m++) {
            u0[m] = C[m][0]*v0[0] + C[m][1]*v0[1] + C[m][2]*v0[2];
            u1[m] = C[m][0]*v1[0] + C[m][1]*v1[1] + C[m][2]*v1[2];
            u2[m] = C[m][0]*v2[0] + C[m][1]*v2[1] + C[m][2]*v2[2];
        }
        double n0 = sqrt(u0[0]*u0[0] + u0[1]*u0[1] + u0[2]*u0[2]);
        if (n0 > 1e-150) { u0[0] /= n0; u0[1] /= n0; u0[2] /= n0; }
        else { u0[0] = 1; u0[1] = 0; u0[2] = 0; n0 = 0; }
        double d01 = u0[0]*u1[0] + u0[1]*u1[1] + u0[2]*u1[2];
        for (int m = 0; m < 3; m++) u1[m] -= d01 * u0[m];
        double n1 = sqrt(u1[0]*u1[0] + u1[1]*u1[1] + u1[2]*u1[2]);
        if (n1 > 1e-150) { u1[0] /= n1; u1[1] /= n1; u1[2] /= n1; }
        else {
            double e[3] = {0,0,0};
            e[(fabs(u0[0]) < 0.9) ? 0 : 1] = 1.0;
            double de = u0[0]*e[0] + u0[1]*e[1] + u0[2]*e[2];
            for (int m = 0; m < 3; m++) u1[m] = e[m] - de * u0[m];
            double nn = sqrt(u1[0]*u1[0] + u1[1]*u1[1] + u1[2]*u1[2]);
            for (int m = 0; m < 3; m++) u1[m] /= nn;
        }
        double d02 = u0[0]*u2[0] + u0[1]*u2[1] + u0[2]*u2[2];
        double d12 = u1[0]*u2[0] + u1[1]*u2[1] + u1[2]*u2[2];
        for (int m = 0; m < 3; m++) u2[m] -= d02 * u0[m] + d12 * u1[m];
        double n2 = sqrt(u2[0]*u2[0] + u2[1]*u2[1] + u2[2]*u2[2]);
        if (n2 > 1e-12 * (n0 + 1e-300)) { u2[0] /= n2; u2[1] /= n2; u2[2] /= n2; }
        else {
            u2[0] = u0[1]*u1[2] - u0[2]*u1[1];
            u2[1] = u0[2]*u1[0] - u0[0]*u1[2];
            u2[2] = u0[0]*u1[1] - u0[1]*u1[0];
        }
        double cx0 = u1[1]*u2[2] - u1[2]*u2[1];
        double cx1 = u1[2]*u2[0] - u1[0]*u2[2];
        double cx2 = u1[0]*u2[1] - u1[1]*u2[0];
        double detU = u0[0]*cx0 + u0[1]*cx1 + u0[2]*cx2;
        double cy0 = v1[1]*v2[2] - v1[2]*v2[1];
        double cy1 = v1[2]*v2[0] - v1[0]*v2[2];
        double cy2 = v1[0]*v2[1] - v1[1]*v2[0];
        double detV = v0[0]*cy0 + v0[1]*cy1 + v0[2]*cy2;
        double dd = (detU * detV >= 0.0) ? 1.0 : -1.0;
        double R[3][3];
        for (int m = 0; m < 3; m++)
            for (int n = 0; n < 3; n++)
                R[m][n] = v0[m]*u0[n] + v1[m]*u1[n] + dd * v2[m]*u2[n];
        double t3[3];
        t3[0] = cb0 - (R[0][0]*ca0 + R[0][1]*ca1 + R[0][2]*ca2);
        t3[1] = cb1 - (R[1][0]*ca0 + R[1][1]*ca1 + R[1][2]*ca2);
        t3[2] = cb2 - (R[2][0]*ca0 + R[2][1]*ca1 + R[2][2]*ca2);
        // compose: T_new = concat(T_i, T_old)
        double* To = g_T[b];
        double Rn[9], tn[3];
        for (int m = 0; m < 3; m++) {
            for (int n = 0; n < 3; n++)
                Rn[m*3+n] = R[m][0]*To[0*4+n] + R[m][1]*To[1*4+n] + R[m][2]*To[2*4+n];
            tn[m] = R[m][0]*To[3] + R[m][1]*To[7] + R[m][2]*To[11] + t3[m];
        }
        for (int m = 0; m < 3; m++) {
            for (int n = 0; n < 3; n++) To[m*4+n] = Rn[m*3+n];
            To[m*4+3] = tn[m];
        }
        if (r == nr - 1 && T_out) {
            for (int m = 0; m < 3; m++)
                for (int n = 0; n < 4; n++)
                    T_out[b * 12 + m * 4 + n] = (float)To[m * 4 + n];
        }
    }
}

// ---------------- launch ----------------
extern "C" void kernel_launch(void* const* d_in, const int* in_sizes, int n_in,
                              void* d_out, int out_size)
{
    const float* src   = (const float*)d_in[0];
    const float* ref   = (const float*)d_in[1];
    const float* beta  = (const float*)d_in[2];
    const float* alpha = (const float*)d_in[3];
    const int*   nreg  = (n_in > 4) ? (const int*)d_in[4] : nullptr;
    const int*   nsk   = (n_in > 5) ? (const int*)d_in[5] : nullptr;

    float* out = (float*)d_out;
    const long permN = (long)BB * NPT * NPT;
    long off = (long)out_size - permN;
    if (off < 0) off = 0;
    float* perm_out = out + off;
    float* T_out = (off >= BB * 12) ? out : nullptr;

    k_init<<<64, 256>>>(ref);
    const int RMAX = 3, SMAX = 5;
    dim3 gridRC(NPT / 32, BB);
    for (int r = 0; r < RMAX; r++) {
        k_prep<<<64, 256>>>(nreg, r, src);
        for (int s = 0; s < SMAX; s++) {
            k_row<<<gridRC, 256>>>(nreg, nsk, r, s, beta, alpha);
            k_col<<<gridRC, 256>>>(nreg, nsk, r, s, beta, alpha);
        }
        k_consume<<<gridRC, 256>>>(nreg, r, beta, alpha, perm_out);
        k_fit<<<BB, 256>>>(nreg, r, T_out);
    }
}

// round 4
// speedup vs baseline: 1.0005x; 1.0005x over previous
#include <cuda_runtime.h>
#include <math.h>

#define BB  16
#define NPT 1024
#define EPSW 1e-5f
#define L2E 1.4426950408889634f

// ---------------- scratch (static device globals; no allocations) ----------------
static __device__ float  g_E[BB][NPT][NPT];      // exp(affinity), 64MB, L2-resident
static __device__ float  g_refSoA[BB][6][NPT];   // ref features, SoA
static __device__ float  g_gn[BB][NPT];          // |g_k|^2
static __device__ float  g_featS[BB][6][NPT];    // transformed src features, SoA
static __device__ float  g_fn[BB][NPT];          // |f_j|^2
static __device__ float  g_eu[BB][NPT];          // exp(-u_j)
static __device__ float  g_ev[BB][NPT];          // exp(-v_k)
static __device__ float  g_w[BB][NPT];           // row weights (sum_k perm)
static __device__ float  g_wrx[BB][NPT];
static __device__ float  g_wry[BB][NPT];
static __device__ float  g_wrz[BB][NPT];
static __device__ double g_T[BB][12];            // accumulated transform, row-major 3x4

__device__ __forceinline__ float fast_ex2(float x){ float y; asm("ex2.approx.ftz.f32 %0, %1;" : "=f"(y) : "f"(x)); return y; }
__device__ __forceinline__ int dval(const int* p, int d){ return p ? __ldg(p) : d; }

// ---------------- init: ref -> SoA, |g|^2, transform = I ----------------
__global__ void k_init(const float* __restrict__ ref)
{
    int idx = blockIdx.x * 256 + threadIdx.x;
    if (idx < BB * NPT) {
        int b = idx >> 10, k = idx & 1023;
        const float* p = ref + (size_t)idx * 6;
        float n = 0.f;
#pragma unroll
        for (int c = 0; c < 6; c++) { float x = p[c]; g_refSoA[b][c][k] = x; n += x * x; }
        g_gn[b][k] = n;
    }
    if (idx < BB) {
        double* T = g_T[idx];
#pragma unroll
        for (int m = 0; m < 3; m++)
#pragma unroll
            for (int c = 0; c < 4; c++) T[m * 4 + c] = (m == c) ? 1.0 : 0.0;
    }
}

// ---------------- prep: src_t = R*src + t, features SoA ----------------
__global__ void k_prep(const int* nreg, int r, const float* __restrict__ src)
{
    if (r >= dval(nreg, 3)) return;
    int idx = blockIdx.x * 256 + threadIdx.x;
    if (idx >= BB * NPT) return;
    int b = idx >> 10, j = idx & 1023;
    const double* T = g_T[b];
    const float* p = src + (size_t)idx * 6;
    float x = p[0], y = p[1], z = p[2], n3 = p[3], n4 = p[4], n5 = p[5];
    float q0 = (float)(T[0] * x + T[1] * y + T[2]  * z + T[3]);
    float q1 = (float)(T[4] * x + T[5] * y + T[6]  * z + T[7]);
    float q2 = (float)(T[8] * x + T[9] * y + T[10] * z + T[11]);
    g_featS[b][0][j] = q0; g_featS[b][1][j] = q1; g_featS[b][2][j] = q2;
    g_featS[b][3][j] = n3; g_featS[b][4][j] = n4; g_featS[b][5][j] = n5;
    g_fn[b][j] = q0*q0 + q1*q1 + q2*q2 + n3*n3 + n4*n4 + n5*n5;
}

// ---------------- mat: E = exp(a), fused with first row pass (ev == 1) ----------------
__global__ void __launch_bounds__(256) k_mat(const int* nreg, int r,
                                             const float* __restrict__ beta_, const float* __restrict__ alpha_)
{
    if (r >= dval(nreg, 3)) return;
    int b = blockIdx.y;
    __shared__ float gs[6][NPT];
    __shared__ float pk[NPT];
    float bl = beta_[b] * L2E;
    for (int i = threadIdx.x; i < NPT; i += 256) {
#pragma unroll
        for (int c = 0; c < 6; c++) gs[c][i] = g_refSoA[b][c][i];
        pk[i] = bl * g_gn[b][i];
    }
    __syncthreads();
    int warp = threadIdx.x >> 5, lane = threadIdx.x & 31;
    int j0 = blockIdx.x * 32 + warp * 4;
    float al = alpha_[b];
    float wj[4][6], cj[4];
#pragma unroll
    for (int t = 0; t < 4; t++) {
        int j = j0 + t;
#pragma unroll
        for (int c = 0; c < 6; c++) wj[t][c] = 2.f * bl * g_featS[b][c][j];
        cj[t] = bl * (al - g_fn[b][j]);
    }
    float* E0 = &g_E[b][j0][0];
    float acc[4] = {0.f, 0.f, 0.f, 0.f};
#pragma unroll 2
    for (int i = 0; i < 32; i++) {
        int k = i * 32 + lane;
        float G[6];
#pragma unroll
        for (int c = 0; c < 6; c++) G[c] = gs[c][k];
        float P = pk[k];
#pragma unroll
        for (int t = 0; t < 4; t++) {
            float a = cj[t] - P;
#pragma unroll
            for (int c = 0; c < 6; c++) a = fmaf(wj[t][c], G[c], a);
            float e = fast_ex2(a);
            E0[t * NPT + k] = e;
            acc[t] += e;
        }
    }
#pragma unroll
    for (int t = 0; t < 4; t++)
#pragma unroll
        for (int o = 16; o; o >>= 1) acc[t] += __shfl_xor_sync(0xffffffffu, acc[t], o);
    if (lane == 0) {
#pragma unroll
        for (int t = 0; t < 4; t++) g_eu[b][j0 + t] = 1.f / (1.f + acc[t]);
    }
}

// ---------------- col pass: ev_k = 1/(1 + sum_j E_jk * eu_j) ----------------
__global__ void __launch_bounds__(256) k_colp(const int* nreg, const int* nsk, int r, int s)
{
    if (r >= dval(nreg, 3) || s >= dval(nsk, 5)) return;
    int b = blockIdx.y;
    __shared__ float eus[NPT];
    __shared__ float red[4][64];
    for (int i = threadIdx.x; i < NPT; i += 256) eus[i] = g_eu[b][i];
    __syncthreads();
    int t = threadIdx.x;
    int kc = blockIdx.x * 64 + (t & 63);
    int q  = t >> 6;                         // j-quarter
    const float* Ep = &g_E[b][q * 256][0] + kc;
    const float* eq = &eus[q * 256];
    float acc = 0.f;
#pragma unroll 8
    for (int j = 0; j < 256; j++)
        acc = fmaf(Ep[(size_t)j * NPT], eq[j], acc);
    red[q][t & 63] = acc;
    __syncthreads();
    if (t < 64) {
        float s4 = red[0][t] + red[1][t] + red[2][t] + red[3][t];
        g_ev[b][blockIdx.x * 64 + t] = 1.f / (1.f + s4);
    }
}

// ---------------- row pass: eu_j = 1/(1 + sum_k E_jk * ev_k) ----------------
__global__ void __launch_bounds__(256) k_rowp(const int* nreg, const int* nsk, int r, int s)
{
    if (r >= dval(nreg, 3) || s >= dval(nsk, 5)) return;
    int b = blockIdx.y;
    __shared__ float evs[NPT];
    for (int i = threadIdx.x; i < NPT; i += 256) evs[i] = g_ev[b][i];
    __syncthreads();
    int warp = threadIdx.x >> 5, lane = threadIdx.x & 31;
    int j0 = blockIdx.x * 32 + warp * 4;
    const float* E0 = &g_E[b][j0][0];
    float a0 = 0.f, a1 = 0.f, a2 = 0.f, a3 = 0.f;
#pragma unroll 4
    for (int i = 0; i < 32; i++) {
        int k = i * 32 + lane;
        float ev = evs[k];
        a0 = fmaf(E0[k],           ev, a0);
        a1 = fmaf(E0[NPT + k],     ev, a1);
        a2 = fmaf(E0[2 * NPT + k], ev, a2);
        a3 = fmaf(E0[3 * NPT + k], ev, a3);
    }
#pragma unroll
    for (int o = 16; o; o >>= 1) {
        a0 += __shfl_xor_sync(0xffffffffu, a0, o);
        a1 += __shfl_xor_sync(0xffffffffu, a1, o);
        a2 += __shfl_xor_sync(0xffffffffu, a2, o);
        a3 += __shfl_xor_sync(0xffffffffu, a3, o);
    }
    if (lane == 0) {
        g_eu[b][j0 + 0] = 1.f / (1.f + a0);
        g_eu[b][j0 + 1] = 1.f / (1.f + a1);
        g_eu[b][j0 + 2] = 1.f / (1.f + a2);
        g_eu[b][j0 + 3] = 1.f / (1.f + a3);
    }
}

// ---------------- consume: row sums, perm @ ref_xyz, (last iter) write perm ----------------
__global__ void __launch_bounds__(256) k_consume(const int* nreg, int r, float* __restrict__ perm_out)
{
    int nr = dval(nreg, 3);
    if (r >= nr) return;
    bool last = (r == nr - 1);
    int b = blockIdx.y;
    __shared__ float gx[NPT], gy[NPT], gz[NPT], evs[NPT];
    for (int i = threadIdx.x; i < NPT; i += 256) {
        gx[i] = g_refSoA[b][0][i];
        gy[i] = g_refSoA[b][1][i];
        gz[i] = g_refSoA[b][2][i];
        evs[i] = g_ev[b][i];
    }
    __syncthreads();
    int warp = threadIdx.x >> 5, lane = threadIdx.x & 31;
    int j0 = blockIdx.x * 32 + warp * 4;
    float eu[4];
#pragma unroll
    for (int t = 0; t < 4; t++) eu[t] = g_eu[b][j0 + t];
    const float* E0 = &g_E[b][j0][0];
    float S[4] = {0,0,0,0}, SX[4] = {0,0,0,0}, SY[4] = {0,0,0,0}, SZ[4] = {0,0,0,0};
    if (last) {
        float* pb[4];
#pragma unroll
        for (int t = 0; t < 4; t++) pb[t] = perm_out + ((size_t)(b * NPT + j0 + t)) * NPT;
#pragma unroll 2
        for (int i = 0; i < 32; i++) {
            int k = i * 32 + lane;
            float ev = evs[k], X = gx[k], Y = gy[k], Z = gz[k];
#pragma unroll
            for (int t = 0; t < 4; t++) {
                float e = E0[t * NPT + k] * ev;
                S[t] += e;
                SX[t] = fmaf(e, X, SX[t]);
                SY[t] = fmaf(e, Y, SY[t]);
                SZ[t] = fmaf(e, Z, SZ[t]);
                pb[t][k] = e * eu[t];
            }
        }
    } else {
#pragma unroll 2
        for (int i = 0; i < 32; i++) {
            int k = i * 32 + lane;
            float ev = evs[k], X = gx[k], Y = gy[k], Z = gz[k];
#pragma unroll
            for (int t = 0; t < 4; t++) {
                float e = E0[t * NPT + k] * ev;
                S[t] += e;
                SX[t] = fmaf(e, X, SX[t]);
                SY[t] = fmaf(e, Y, SY[t]);
                SZ[t] = fmaf(e, Z, SZ[t]);
            }
        }
    }
#pragma unroll
    for (int t = 0; t < 4; t++) {
#pragma unroll
        for (int o = 16; o; o >>= 1) {
            S[t]  += __shfl_xor_sync(0xffffffffu, S[t],  o);
            SX[t] += __shfl_xor_sync(0xffffffffu, SX[t], o);
            SY[t] += __shfl_xor_sync(0xffffffffu, SY[t], o);
            SZ[t] += __shfl_xor_sync(0xffffffffu, SZ[t], o);
        }
    }
    if (lane == 0) {
#pragma unroll
        for (int t = 0; t < 4; t++) {
            int j = j0 + t;
            float W = S[t] * eu[t];
            g_w[b][j] = W;
            float inv = 1.f / (W + EPSW);
            g_wrx[b][j] = SX[t] * eu[t] * inv;
            g_wry[b][j] = SY[t] * eu[t] * inv;
            g_wrz[b][j] = SZ[t] * eu[t] * inv;
        }
    }
}

// ---------------- fit: weighted Kabsch (fp64 Jacobi SVD) + compose transform ----------------
__global__ void __launch_bounds__(256) k_fit(const int* nreg, int r, float* __restrict__ T_out)
{
    int nr = dval(nreg, 3);
    if (r >= nr) return;
    int b = blockIdx.x;
    int lane = threadIdx.x & 31, warp = threadIdx.x >> 5;
    __shared__ double sred[8][9];
    __shared__ double sc[8];

    // phase 1: W, sum w*a, sum w*b
    double acc[7] = {0,0,0,0,0,0,0};
    for (int j = threadIdx.x; j < NPT; j += 256) {
        double w  = g_w[b][j];
        double ax = g_featS[b][0][j], ay = g_featS[b][1][j], az = g_featS[b][2][j];
        double bx = g_wrx[b][j], by = g_wry[b][j], bz = g_wrz[b][j];
        acc[0] += w;
        acc[1] += w*ax; acc[2] += w*ay; acc[3] += w*az;
        acc[4] += w*bx; acc[5] += w*by; acc[6] += w*bz;
    }
#pragma unroll
    for (int i = 0; i < 7; i++)
#pragma unroll
        for (int o = 16; o; o >>= 1) acc[i] += __shfl_xor_sync(0xffffffffu, acc[i], o);
    if (lane == 0)
#pragma unroll
        for (int i = 0; i < 7; i++) sred[warp][i] = acc[i];
    __syncthreads();
    if (threadIdx.x == 0) {
        double tot[7] = {0,0,0,0,0,0,0};
        for (int w = 0; w < 8; w++)
            for (int i = 0; i < 7; i++) tot[i] += sred[w][i];
        double den = tot[0] + 1e-5;
        sc[0] = den;
        for (int i = 0; i < 6; i++) sc[1 + i] = tot[1 + i] / den;
    }
    __syncthreads();
    double den = sc[0];
    double ca0 = sc[1], ca1 = sc[2], ca2 = sc[3];
    double cb0 = sc[4], cb1 = sc[5], cb2 = sc[6];

    // phase 2: cov = sum wn (a-ca)(b-cb)^T
    double cv[9] = {0,0,0,0,0,0,0,0,0};
    for (int j = threadIdx.x; j < NPT; j += 256) {
        double wn = (double)g_w[b][j] / den;
        double ax = g_featS[b][0][j] - ca0, ay = g_featS[b][1][j] - ca1, az = g_featS[b][2][j] - ca2;
        double bx = g_wrx[b][j] - cb0, by = g_wry[b][j] - cb1, bz = g_wrz[b][j] - cb2;
        cv[0] += wn*ax*bx; cv[1] += wn*ax*by; cv[2] += wn*ax*bz;
        cv[3] += wn*ay*bx; cv[4] += wn*ay*by; cv[5] += wn*ay*bz;
        cv[6] += wn*az*bx; cv[7] += wn*az*by; cv[8] += wn*az*bz;
    }
#pragma unroll
    for (int i = 0; i < 9; i++)
#pragma unroll
        for (int o = 16; o; o >>= 1) cv[i] += __shfl_xor_sync(0xffffffffu, cv[i], o);
    if (lane == 0)
#pragma unroll
        for (int i = 0; i < 9; i++) sred[warp][i] = cv[i];
    __syncthreads();

    if (threadIdx.x == 0) {
        double C[3][3];
        {
            double tot[9] = {0,0,0,0,0,0,0,0,0};
            for (int w = 0; w < 8; w++)
                for (int i = 0; i < 9; i++) tot[i] += sred[w][i];
            for (int m = 0; m < 3; m++)
                for (int n = 0; n < 3; n++) C[m][n] = tot[m * 3 + n];
        }
        // A = C^T C, Jacobi eigendecomposition -> V
        double A[3][3];
        for (int i = 0; i < 3; i++)
            for (int j = 0; j < 3; j++)
                A[i][j] = C[0][i]*C[0][j] + C[1][i]*C[1][j] + C[2][i]*C[2][j];
        double V[3][3] = {{1,0,0},{0,1,0},{0,0,1}};
        const int PP[3] = {0,0,1}, QQ[3] = {1,2,2};
        for (int sweep = 0; sweep < 30; sweep++) {
            double off = A[0][1]*A[0][1] + A[0][2]*A[0][2] + A[1][2]*A[1][2];
            if (off < 1e-26) break;
            for (int pi = 0; pi < 3; pi++) {
                int p = PP[pi], q = QQ[pi];
                double apq = A[p][q];
                if (fabs(apq) < 1e-300) continue;
                double theta = (A[q][q] - A[p][p]) / (2.0 * apq);
                double tt = ((theta >= 0.0) ? 1.0 : -1.0) / (fabs(theta) + sqrt(theta*theta + 1.0));
                double c = 1.0 / sqrt(tt*tt + 1.0), sn = tt * c;
                int m = 3 - p - q;
                double amp = A[m][p], amq = A[m][q];
                double app = A[p][p], aqq = A[q][q];
                A[p][p] = app - tt * apq;
                A[q][q] = aqq + tt * apq;
                A[p][q] = A[q][p] = 0.0;
                A[m][p] = A[p][m] = c*amp - sn*amq;
                A[m][q] = A[q][m] = sn*amp + c*amq;
                for (int mm = 0; mm < 3; mm++) {
                    double vp = V[mm][p], vq = V[mm][q];
                    V[mm][p] = c*vp - sn*vq;
                    V[mm][q] = sn*vp + c*vq;
                }
            }
        }
        double lam[3] = {A[0][0], A[1][1], A[2][2]};
        for (int i = 0; i < 2; i++)
            for (int j = i + 1; j < 3; j++)
                if (lam[j] > lam[i]) {
                    double tl = lam[i]; lam[i] = lam[j]; lam[j] = tl;
                    for (int m = 0; m < 3; m++) { double tv = V[m][i]; V[m][i] = V[m][j]; V[m][j] = tv; }
                }
        double v0[3] = {V[0][0], V[1][0], V[2][0]};
        double v1[3] = {V[0][1], V[1][1], V[2][1]};
        double v2[3] = {V[0][2], V[1][2], V[2][2]};
        double u0[3], u1[3], u2[3];
        for (int m = 0; m < 3; m++) {
            u0[m] = C[m][0]*v0[0] + C[m][1]*v0[1] + C[m][2]*v0[2];
            u1[m] = C[m][0]*v1[0] + C[m][1]*v1[1] + C[m][2]*v1[2];
            u2[m] = C[m][0]*v2[0] + C[m][1]*v2[1] + C[m][2]*v2[2];
        }
        double n0 = sqrt(u0[0]*u0[0] + u0[1]*u0[1] + u0[2]*u0[2]);
        if (n0 > 1e-150) { u0[0] /= n0; u0[1] /= n0; u0[2] /= n0; }
        else { u0[0] = 1; u0[1] = 0; u0[2] = 0; n0 = 0; }
        double d01 = u0[0]*u1[0] + u0[1]*u1[1] + u0[2]*u1[2];
        for (int m = 0; m < 3; m++) u1[m] -= d01 * u0[m];
        double n1 = sqrt(u1[0]*u1[0] + u1[1]*u1[1] + u1[2]*u1[2]);
        if (n1 > 1e-150) { u1[0] /= n1; u1[1] /= n1; u1[2] /= n1; }
        else {
            double e[3] = {0,0,0};
            e[(fabs(u0[0]) < 0.9) ? 0 : 1] = 1.0;
            double de = u0[0]*e[0] + u0[1]*e[1] + u0[2]*e[2];
            for (int m = 0; m < 3; m++) u1[m] = e[m] - de * u0[m];
            double nn = sqrt(u1[0]*u1[0] + u1[1]*u1[1] + u1[2]*u1[2]);
            for (int m = 0; m < 3; m++) u1[m] /= nn;
        }
        double d02 = u0[0]*u2[0] + u0[1]*u2[1] + u0[2]*u2[2];
        double d12 = u1[0]*u2[0] + u1[1]*u2[1] + u1[2]*u2[2];
        for (int m = 0; m < 3; m++) u2[m] -= d02 * u0[m] + d12 * u1[m];
        double n2 = sqrt(u2[0]*u2[0] + u2[1]*u2[1] + u2[2]*u2[2]);
        if (n2 > 1e-12 * (n0 + 1e-300)) { u2[0] /= n2; u2[1] /= n2; u2[2] /= n2; }
        else {
            u2[0] = u0[1]*u1[2] - u0[2]*u1[1];
            u2[1] = u0[2]*u1[0] - u0[0]*u1[2];
            u2[2] = u0[0]*u1[1] - u0[1]*u1[0];
        }
        double cx0 = u1[1]*u2[2] - u1[2]*u2[1];
        double cx1 = u1[2]*u2[0] - u1[0]*u2[2];
        double cx2 = u1[0]*u2[1] - u1[1]*u2[0];
        double detU = u0[0]*cx0 + u0[1]*cx1 + u0[2]*cx2;
        double cy0 = v1[1]*v2[2] - v1[2]*v2[1];
        double cy1 = v1[2]*v2[0] - v1[0]*v2[2];
        double cy2 = v1[0]*v2[1] - v1[1]*v2[0];
        double detV = v0[0]*cy0 + v0[1]*cy1 + v0[2]*cy2;
        double dd = (detU * detV >= 0.0) ? 1.0 : -1.0;
        double R[3][3];
        for (int m = 0; m < 3; m++)
            for (int n = 0; n < 3; n++)
                R[m][n] = v0[m]*u0[n] + v1[m]*u1[n] + dd * v2[m]*u2[n];
        double t3[3];
        t3[0] = cb0 - (R[0][0]*ca0 + R[0][1]*ca1 + R[0][2]*ca2);
        t3[1] = cb1 - (R[1][0]*ca0 + R[1][1]*ca1 + R[1][2]*ca2);
        t3[2] = cb2 - (R[2][0]*ca0 + R[2][1]*ca1 + R[2][2]*ca2);
        // compose: T_new = concat(T_i, T_old)
        double* To = g_T[b];
        double Rn[9], tn[3];
        for (int m = 0; m < 3; m++) {
            for (int n = 0; n < 3; n++)
                Rn[m*3+n] = R[m][0]*To[0*4+n] + R[m][1]*To[1*4+n] + R[m][2]*To[2*4+n];
            tn[m] = R[m][0]*To[3] + R[m][1]*To[7] + R[m][2]*To[11] + t3[m];
        }
        for (int m = 0; m < 3; m++) {
            for (int n = 0; n < 3; n++) To[m*4+n] = Rn[m*3+n];
            To[m*4+3] = tn[m];
        }
        if (r == nr - 1 && T_out) {
            for (int m = 0; m < 3; m++)
                for (int n = 0; n < 4; n++)
                    T_out[b * 12 + m * 4 + n] = (float)To[m * 4 + n];
        }
    }
}

// ---------------- launch ----------------
extern "C" void kernel_launch(void* const* d_in, const int* in_sizes, int n_in,
                              void* d_out, int out_size)
{
    const float* src   = (const float*)d_in[0];
    const float* ref   = (const float*)d_in[1];
    const float* beta  = (const float*)d_in[2];
    const float* alpha = (const float*)d_in[3];
    const int*   nreg  = (n_in > 4) ? (const int*)d_in[4] : nullptr;
    const int*   nsk   = (n_in > 5) ? (const int*)d_in[5] : nullptr;

    float* out = (float*)d_out;
    const long permN = (long)BB * NPT * NPT;
    long off = (long)out_size - permN;
    if (off < 0) off = 0;
    float* perm_out = out + off;
    float* T_out = (off >= BB * 12) ? out : nullptr;

    k_init<<<64, 256>>>(ref);
    const int RMAX = 3, SMAX = 5;
    dim3 gridRow(NPT / 32, BB);
    dim3 gridCol(NPT / 64, BB);
    for (int r = 0; r < RMAX; r++) {
        k_prep<<<64, 256>>>(nreg, r, src);
        k_mat<<<gridRow, 256>>>(nreg, r, beta, alpha);        // E + row pass s=0 (ev==1)
        for (int s = 0; s < SMAX; s++) {
            k_colp<<<gridCol, 256>>>(nreg, nsk, r, s);
            if (s < SMAX - 1)
                k_rowp<<<gridRow, 256>>>(nreg, nsk, r, s + 1);
        }
        k_consume<<<gridRow, 256>>>(nreg, r, perm_out);
        k_fit<<<BB, 256>>>(nreg, r, T_out);
    }
}

// round 6
// speedup vs baseline: 1.3561x; 1.3554x over previous
#include <cuda_runtime.h>
#include <cuda_fp16.h>
#include <math.h>

#define BB  16
#define NPT 1024
#define EPSW 1e-5f
#define L2E 1.4426950408889634f

// ---------------- scratch (static device globals; no allocations) ----------------
static __device__ __half g_Eh[BB][NPT][NPT];     // exp(affinity) fp16, 32MB, L2-resident
static __device__ float  g_part[4][BB][NPT];     // column-pass partial sums (4 j-chunks)
static __device__ float  g_refSoA[BB][6][NPT];   // ref features, SoA
static __device__ float  g_gn[BB][NPT];          // |g_k|^2
static __device__ float  g_featS[BB][6][NPT];    // transformed src features, SoA
static __device__ float  g_fn[BB][NPT];          // |f_j|^2
static __device__ float  g_eu[BB][NPT];          // exp(-u_j)
static __device__ float  g_w[BB][NPT];           // row weights (sum_k perm)
static __device__ float  g_wrx[BB][NPT];
static __device__ float  g_wry[BB][NPT];
static __device__ float  g_wrz[BB][NPT];
static __device__ double g_T[BB][12];            // accumulated transform, row-major 3x4

__device__ __forceinline__ float fast_ex2(float x){ float y; asm("ex2.approx.ftz.f32 %0, %1;" : "=f"(y) : "f"(x)); return y; }
__device__ __forceinline__ int dval(const int* p, int d){ return p ? __ldg(p) : d; }

// ---------------- init: ref -> SoA, |g|^2, transform = I ----------------
__global__ void k_init(const float* __restrict__ ref)
{
    int idx = blockIdx.x * 256 + threadIdx.x;
    if (idx < BB * NPT) {
        int b = idx >> 10, k = idx & 1023;
        const float* p = ref + (size_t)idx * 6;
        float n = 0.f;
#pragma unroll
        for (int c = 0; c < 6; c++) { float x = p[c]; g_refSoA[b][c][k] = x; n += x * x; }
        g_gn[b][k] = n;
    }
    if (idx < BB) {
        double* T = g_T[idx];
#pragma unroll
        for (int m = 0; m < 3; m++)
#pragma unroll
            for (int c = 0; c < 4; c++) T[m * 4 + c] = (m == c) ? 1.0 : 0.0;
    }
}

// ---------------- prep: src_t = R*src + t, features SoA ----------------
__global__ void k_prep(const int* nreg, int r, const float* __restrict__ src)
{
    if (r >= dval(nreg, 3)) return;
    int idx = blockIdx.x * 256 + threadIdx.x;
    if (idx >= BB * NPT) return;
    int b = idx >> 10, j = idx & 1023;
    const double* T = g_T[b];
    const float* p = src + (size_t)idx * 6;
    float x = p[0], y = p[1], z = p[2], n3 = p[3], n4 = p[4], n5 = p[5];
    float q0 = (float)(T[0] * x + T[1] * y + T[2]  * z + T[3]);
    float q1 = (float)(T[4] * x + T[5] * y + T[6]  * z + T[7]);
    float q2 = (float)(T[8] * x + T[9] * y + T[10] * z + T[11]);
    g_featS[b][0][j] = q0; g_featS[b][1][j] = q1; g_featS[b][2][j] = q2;
    g_featS[b][3][j] = n3; g_featS[b][4][j] = n4; g_featS[b][5][j] = n5;
    g_fn[b][j] = q0*q0 + q1*q1 + q2*q2 + n3*n3 + n4*n4 + n5*n5;
}

// ---------------- mat: E = exp(a) (fp16), fused with first row pass (ev == 1) ----------------
__global__ void __launch_bounds__(256) k_mat(const int* nreg, int r,
                                             const float* __restrict__ beta_, const float* __restrict__ alpha_)
{
    if (r >= dval(nreg, 3)) return;
    int b = blockIdx.y;
    __shared__ float gs[6][NPT];
    __shared__ float pk[NPT];
    float bl = beta_[b] * L2E;
    for (int i = threadIdx.x; i < NPT; i += 256) {
#pragma unroll
        for (int c = 0; c < 6; c++) gs[c][i] = g_refSoA[b][c][i];
        pk[i] = bl * g_gn[b][i];
    }
    __syncthreads();
    int warp = threadIdx.x >> 5, lane = threadIdx.x & 31;
    int j0 = blockIdx.x * 32 + warp * 4;
    float al = alpha_[b];
    float wj[4][6], cj[4];
#pragma unroll
    for (int t = 0; t < 4; t++) {
        int j = j0 + t;
#pragma unroll
        for (int c = 0; c < 6; c++) wj[t][c] = 2.f * bl * g_featS[b][c][j];
        cj[t] = bl * (al - g_fn[b][j]);
    }
    __half* E0 = &g_Eh[b][j0][0];
    float acc[4] = {0.f, 0.f, 0.f, 0.f};
#pragma unroll 2
    for (int i = 0; i < 32; i++) {
        int k = i * 32 + lane;
        float G[6];
#pragma unroll
        for (int c = 0; c < 6; c++) G[c] = gs[c][k];
        float P = pk[k];
#pragma unroll
        for (int t = 0; t < 4; t++) {
            float a = cj[t] - P;
#pragma unroll
            for (int c = 0; c < 6; c++) a = fmaf(wj[t][c], G[c], a);
            float e = fast_ex2(a);
            E0[t * NPT + k] = __float2half(e);
            acc[t] += e;
        }
    }
#pragma unroll
    for (int t = 0; t < 4; t++)
#pragma unroll
        for (int o = 16; o; o >>= 1) acc[t] += __shfl_xor_sync(0xffffffffu, acc[t], o);
    if (lane == 0) {
#pragma unroll
        for (int t = 0; t < 4; t++) g_eu[b][j0 + t] = 1.f / (1.f + acc[t]);
    }
}

// ---------------- col pass (partial): part[jc][b][k] = sum_{j in chunk} E_jk * eu_j ----------------
__global__ void __launch_bounds__(256) k_colp(const int* nreg, const int* nsk, int r, int s)
{
    if (r >= dval(nreg, 3) || s >= dval(nsk, 5)) return;
    int b  = blockIdx.y;
    int kc = blockIdx.x & 15;        // 16 chunks of 64 k-columns
    int jc = blockIdx.x >> 4;        // 4 chunks of 256 j-rows
    int t = threadIdx.x, w = t >> 5, lane = t & 31;
    __shared__ float  eus[256];
    __shared__ float2 red[8][32];
    eus[t] = g_eu[b][jc * 256 + t];
    __syncthreads();
    const __half2* Ep = (const __half2*)(&g_Eh[b][jc * 256 + w * 32][0]) + kc * 32 + lane;
    float ax = 0.f, ay = 0.f;
#pragma unroll
    for (int jj = 0; jj < 32; jj++) {
        float2 f = __half22float2(Ep[(size_t)jj * (NPT / 2)]);
        float e = eus[w * 32 + jj];
        ax = fmaf(f.x, e, ax);
        ay = fmaf(f.y, e, ay);
    }
    red[w][lane] = make_float2(ax, ay);
    __syncthreads();
    if (t < 32) {
        float sx = 0.f, sy = 0.f;
#pragma unroll
        for (int ww = 0; ww < 8; ww++) { sx += red[ww][t].x; sy += red[ww][t].y; }
        ((float2*)&g_part[jc][b][kc * 64])[t] = make_float2(sx, sy);
    }
}

// ---------------- row pass: eu_j = 1/(1 + sum_k E_jk * ev_k), ev from partials ----------------
__global__ void __launch_bounds__(256) k_rowp(const int* nreg, const int* nsk, int r, int s)
{
    if (r >= dval(nreg, 3) || s >= dval(nsk, 5)) return;
    int b = blockIdx.y;
    __shared__ float evs[NPT];
    for (int i = threadIdx.x; i < NPT; i += 256)
        evs[i] = 1.f / (1.f + g_part[0][b][i] + g_part[1][b][i] + g_part[2][b][i] + g_part[3][b][i]);
    __syncthreads();
    int w = threadIdx.x >> 5, lane = threadIdx.x & 31;
    int j = blockIdx.x * 8 + w;
    const __half2* Ej = (const __half2*)(&g_Eh[b][j][0]) + lane;
    const float2*  ev2 = (const float2*)evs;
    float acc = 0.f;
#pragma unroll
    for (int i = 0; i < 16; i++) {
        float2 f = __half22float2(Ej[i * 32]);
        float2 e = ev2[i * 32 + lane];
        acc = fmaf(f.x, e.x, fmaf(f.y, e.y, acc));
    }
#pragma unroll
    for (int o = 16; o; o >>= 1) acc += __shfl_xor_sync(0xffffffffu, acc, o);
    if (lane == 0) g_eu[b][j] = 1.f / (1.f + acc);
}

// ---------------- consume: exact fp32 recompute of E; row sums, perm @ ref_xyz, perm write ----------------
__global__ void __launch_bounds__(256) k_consume(const int* nreg, int r,
                                                 const float* __restrict__ beta_, const float* __restrict__ alpha_,
                                                 float* __restrict__ perm_out)
{
    int nr = dval(nreg, 3);
    if (r >= nr) return;
    bool last = (r == nr - 1);
    int b = blockIdx.y;
    __shared__ float gs[6][NPT];
    __shared__ float pk[NPT];
    __shared__ float evs[NPT];
    float bl = beta_[b] * L2E;
    for (int i = threadIdx.x; i < NPT; i += 256) {
#pragma unroll
        for (int c = 0; c < 6; c++) gs[c][i] = g_refSoA[b][c][i];
        pk[i] = bl * g_gn[b][i];
        evs[i] = 1.f / (1.f + g_part[0][b][i] + g_part[1][b][i] + g_part[2][b][i] + g_part[3][b][i]);
    }
    __syncthreads();
    int warp = threadIdx.x >> 5, lane = threadIdx.x & 31;
    int j0 = blockIdx.x * 32 + warp * 4;
    float al = alpha_[b];
    float wj[4][6], cj[4], eu[4];
#pragma unroll
    for (int t = 0; t < 4; t++) {
        int j = j0 + t;
#pragma unroll
        for (int c = 0; c < 6; c++) wj[t][c] = 2.f * bl * g_featS[b][c][j];
        cj[t] = bl * (al - g_fn[b][j]);
        eu[t] = g_eu[b][j];
    }
    float S[4] = {0,0,0,0}, SX[4] = {0,0,0,0}, SY[4] = {0,0,0,0}, SZ[4] = {0,0,0,0};
    if (last) {
        float* pb[4];
#pragma unroll
        for (int t = 0; t < 4; t++) pb[t] = perm_out + ((size_t)(b * NPT + j0 + t)) * NPT;
#pragma unroll 2
        for (int i = 0; i < 32; i++) {
            int k = i * 32 + lane;
            float G[6];
#pragma unroll
            for (int c = 0; c < 6; c++) G[c] = gs[c][k];
            float P = pk[k], ev = evs[k];
#pragma unroll
            for (int t = 0; t < 4; t++) {
                float a = cj[t] - P;
#pragma unroll
                for (int c = 0; c < 6; c++) a = fmaf(wj[t][c], G[c], a);
                float e = fast_ex2(a) * ev;
                S[t] += e;
                SX[t] = fmaf(e, G[0], SX[t]);
                SY[t] = fmaf(e, G[1], SY[t]);
                SZ[t] = fmaf(e, G[2], SZ[t]);
                pb[t][k] = e * eu[t];
            }
        }
    } else {
#pragma unroll 2
        for (int i = 0; i < 32; i++) {
            int k = i * 32 + lane;
            float G[6];
#pragma unroll
            for (int c = 0; c < 6; c++) G[c] = gs[c][k];
            float P = pk[k], ev = evs[k];
#pragma unroll
            for (int t = 0; t < 4; t++) {
                float a = cj[t] - P;
#pragma unroll
                for (int c = 0; c < 6; c++) a = fmaf(wj[t][c], G[c], a);
                float e = fast_ex2(a) * ev;
                S[t] += e;
                SX[t] = fmaf(e, G[0], SX[t]);
                SY[t] = fmaf(e, G[1], SY[t]);
                SZ[t] = fmaf(e, G[2], SZ[t]);
            }
        }
    }
#pragma unroll
    for (int t = 0; t < 4; t++) {
#pragma unroll
        for (int o = 16; o; o >>= 1) {
            S[t]  += __shfl_xor_sync(0xffffffffu, S[t],  o);
            SX[t] += __shfl_xor_sync(0xffffffffu, SX[t], o);
            SY[t] += __shfl_xor_sync(0xffffffffu, SY[t], o);
            SZ[t] += __shfl_xor_sync(0xffffffffu, SZ[t], o);
        }
    }
    if (lane == 0) {
#pragma unroll
        for (int t = 0; t < 4; t++) {
            int j = j0 + t;
            float W = S[t] * eu[t];
            g_w[b][j] = W;
            float inv = 1.f / (W + EPSW);
            g_wrx[b][j] = SX[t] * eu[t] * inv;
            g_wry[b][j] = SY[t] * eu[t] * inv;
            g_wrz[b][j] = SZ[t] * eu[t] * inv;
        }
    }
}

// ---------------- fit: weighted Kabsch (fp64 Jacobi SVD) + compose transform ----------------
__global__ void __launch_bounds__(256) k_fit(const int* nreg, int r, float* __restrict__ T_out)
{
    int nr = dval(nreg, 3);
    if (r >= nr) return;
    int b = blockIdx.x;
    int lane = threadIdx.x & 31, warp = threadIdx.x >> 5;
    __shared__ double sred[8][9];
    __shared__ double sc[8];

    double acc[7] = {0,0,0,0,0,0,0};
    for (int j = threadIdx.x; j < NPT; j += 256) {
        double w  = g_w[b][j];
        double ax = g_featS[b][0][j], ay = g_featS[b][1][j], az = g_featS[b][2][j];
        double bx = g_wrx[b][j], by = g_wry[b][j], bz = g_wrz[b][j];
        acc[0] += w;
        acc[1] += w*ax; acc[2] += w*ay; acc[3] += w*az;
        acc[4] += w*bx; acc[5] += w*by; acc[6] += w*bz;
    }
#pragma unroll
    for (int i = 0; i < 7; i++)
#pragma unroll
        for (int o = 16; o; o >>= 1) acc[i] += __shfl_xor_sync(0xffffffffu, acc[i], o);
    if (lane == 0)
#pragma unroll
        for (int i = 0; i < 7; i++) sred[warp][i] = acc[i];
    __syncthreads();
    if (threadIdx.x == 0) {
        double tot[7] = {0,0,0,0,0,0,0};
        for (int w = 0; w < 8; w++)
            for (int i = 0; i < 7; i++) tot[i] += sred[w][i];
        double den = tot[0] + 1e-5;
        sc[0] = den;
        for (int i = 0; i < 6; i++) sc[1 + i] = tot[1 + i] / den;
    }
    __syncthreads();
    double den = sc[0];
    double ca0 = sc[1], ca1 = sc[2], ca2 = sc[3];
    double cb0 = sc[4], cb1 = sc[5], cb2 = sc[6];

    double cv[9] = {0,0,0,0,0,0,0,0,0};
    for (int j = threadIdx.x; j < NPT; j += 256) {
        double wn = (double)g_w[b][j] / den;
        double ax = g_featS[b][0][j] - ca0, ay = g_featS[b][1][j] - ca1, az = g_featS[b][2][j] - ca2;
        double bx = g_wrx[b][j] - cb0, by = g_wry[b][j] - cb1, bz = g_wrz[b][j] - cb2;
        cv[0] += wn*ax*bx; cv[1] += wn*ax*by; cv[2] += wn*ax*bz;
        cv[3] += wn*ay*bx; cv[4] += wn*ay*by; cv[5] += wn*ay*bz;
        cv[6] += wn*az*bx; cv[7] += wn*az*by; cv[8] += wn*az*bz;
    }
#pragma unroll
    for (int i = 0; i < 9; i++)
#pragma unroll
        for (int o = 16; o; o >>= 1) cv[i] += __shfl_xor_sync(0xffffffffu, cv[i], o);
    if (lane == 0)
#pragma unroll
        for (int i = 0; i < 9; i++) sred[warp][i] = cv[i];
    __syncthreads();

    if (threadIdx.x == 0) {
        double C[3][3];
        {
            double tot[9] = {0,0,0,0,0,0,0,0,0};
            for (int w = 0; w < 8; w++)
                for (int i = 0; i < 9; i++) tot[i] += sred[w][i];
            for (int m = 0; m < 3; m++)
                for (int n = 0; n < 3; n++) C[m][n] = tot[m * 3 + n];
        }
        double A[3][3];
        for (int i = 0; i < 3; i++)
            for (int j = 0; j < 3; j++)
                A[i][j] = C[0][i]*C[0][j] + C[1][i]*C[1][j] + C[2][i]*C[2][j];
        double V[3][3] = {{1,0,0},{0,1,0},{0,0,1}};
        const int PP[3] = {0,0,1}, QQ[3] = {1,2,2};
        for (int sweep = 0; sweep < 30; sweep++) {
            double off = A[0][1]*A[0][1] + A[0][2]*A[0][2] + A[1][2]*A[1][2];
            if (off < 1e-26) break;
            for (int pi = 0; pi < 3; pi++) {
                int p = PP[pi], q = QQ[pi];
                double apq = A[p][q];
                if (fabs(apq) < 1e-300) continue;
                double theta = (A[q][q] - A[p][p]) / (2.0 * apq);
                double tt = ((theta >= 0.0) ? 1.0 : -1.0) / (fabs(theta) + sqrt(theta*theta + 1.0));
                double c = 1.0 / sqrt(tt*tt + 1.0), sn = tt * c;
                int m = 3 - p - q;
                double amp = A[m][p], amq = A[m][q];
                double app = A[p][p], aqq = A[q][q];
                A[p][p] = app - tt * apq;
                A[q][q] = aqq + tt * apq;
                A[p][q] = A[q][p] = 0.0;
                A[m][p] = A[p][m] = c*amp - sn*amq;
                A[m][q] = A[q][m] = sn*amp + c*amq;
                for (int mm = 0; mm < 3; mm++) {
                    double vp = V[mm][p], vq = V[mm][q];
                    V[mm][p] = c*vp - sn*vq;
                    V[mm][q] = sn*vp + c*vq;
                }
            }
        }
        double lam[3] = {A[0][0], A[1][1], A[2][2]};
        for (int i = 0; i < 2; i++)
            for (int j = i + 1; j < 3; j++)
                if (lam[j] > lam[i]) {
                    double tl = lam[i]; lam[i] = lam[j]; lam[j] = tl;
                    for (int m = 0; m < 3; m++) { double tv = V[m][i]; V[m][i] = V[m][j]; V[m][j] = tv; }
                }
        double v0[3] = {V[0][0], V[1][0], V[2][0]};
        double v1[3] = {V[0][1], V[1][1], V[2][1]};
        double v2[3] = {V[0][2], V[1][2], V[2][2]};
        double u0[3], u1[3], u2[3];
        for (int m = 0; m < 3; m++) {
            u0[m] = C[m][0]*v0[0] + C[m][1]*v0[1] + C[m][2]*v0[2];
            u1[m] = C[m][0]*v1[0] + C[m][1]*v1[1] + C[m][2]*v1[2];
            u2[m] = C[m][0]*v2[0] + C[m][1]*v2[1] + C[m][2]*v2[2];
        }
        double n0 = sqrt(u0[0]*u0[0] + u0[1]*u0[1] + u0[2]*u0[2]);
        if (n0 > 1e-150) { u0[0] /= n0; u0[1] /= n0; u0[2] /= n0; }
        else { u0[0] = 1; u0[1] = 0; u0[2] = 0; n0 = 0; }
        double d01 = u0[0]*u1[0] + u0[1]*u1[1] + u0[2]*u1[2];
        for (int m = 0; m < 3; m++) u1[m] -= d01 * u0[m];
        double n1 = sqrt(u1[0]*u1[0] + u1[1]*u1[1] + u1[2]*u1[2]);
        if (n1 > 1e-150) { u1[0] /= n1; u1[1] /= n1; u1[2] /= n1; }
        else {
            double e[3] = {0,0,0};
            e[(fabs(u0[0]) < 0.9) ? 0 : 1] = 1.0;
            double de = u0[0]*e[0] + u0[1]*e[1] + u0[2]*e[2];
            for (int m = 0; m < 3; m++) u1[m] = e[m] - de * u0[m];
            double nn = sqrt(u1[0]*u1[0] + u1[1]*u1[1] + u1[2]*u1[2]);
            for (int m = 0; m < 3; m++) u1[m] /= nn;
        }
        double d02 = u0[0]*u2[0] + u0[1]*u2[1] + u0[2]*u2[2];
        double d12 = u1[0]*u2[0] + u1[1]*u2[1] + u1[2]*u2[2];
        for (int m = 0; m < 3; m++) u2[m] -= d02 * u0[m] + d12 * u1[m];
        double n2 = sqrt(u2[0]*u2[0] + u2[1]*u2[1] + u2[2]*u2[2]);
        if (n2 > 1e-12 * (n0 + 1e-300)) { u2[0] /= n2; u2[1] /= n2; u2[2] /= n2; }
        else {
            u2[0] = u0[1]*u1[2] - u0[2]*u1[1];
            u2[1] = u0[2]*u1[0] - u0[0]*u1[2];
            u2[2] = u0[0]*u1[1] - u0[1]*u1[0];
        }
        double cx0 = u1[1]*u2[2] - u1[2]*u2[1];
        double cx1 = u1[2]*u2[0] - u1[0]*u2[2];
        double cx2 = u1[0]*u2[1] - u1[1]*u2[0];
        double detU = u0[0]*cx0 + u0[1]*cx1 + u0[2]*cx2;
        double cy0 = v1[1]*v2[2] - v1[2]*v2[1];
        double cy1 = v1[2]*v2[0] - v1[0]*v2[2];
        double cy2 = v1[0]*v2[1] - v1[1]*v2[0];
        double detV = v0[0]*cy0 + v0[1]*cy1 + v0[2]*cy2;
        double dd = (detU * detV >= 0.0) ? 1.0 : -1.0;
        double R[3][3];
        for (int m = 0; m < 3; m++)
            for (int n = 0; n < 3; n++)
                R[m][n] = v0[m]*u0[n] + v1[m]*u1[n] + dd * v2[m]*u2[n];
        double t3[3];
        t3[0] = cb0 - (R[0][0]*ca0 + R[0][1]*ca1 + R[0][2]*ca2);
        t3[1] = cb1 - (R[1][0]*ca0 + R[1][1]*ca1 + R[1][2]*ca2);
        t3[2] = cb2 - (R[2][0]*ca0 + R[2][1]*ca1 + R[2][2]*ca2);
        double* To = g_T[b];
        double Rn[9], tn[3];
        for (int m = 0; m < 3; m++) {
            for (int n = 0; n < 3; n++)
                Rn[m*3+n] = R[m][0]*To[0*4+n] + R[m][1]*To[1*4+n] + R[m][2]*To[2*4+n];
            tn[m] = R[m][0]*To[3] + R[m][1]*To[7] + R[m][2]*To[11] + t3[m];
        }
        for (int m = 0; m < 3; m++) {
            for (int n = 0; n < 3; n++) To[m*4+n] = Rn[m*3+n];
            To[m*4+3] = tn[m];
        }
        if (r == nr - 1 && T_out) {
            for (int m = 0; m < 3; m++)
                for (int n = 0; n < 4; n++)
                    T_out[b * 12 + m * 4 + n] = (float)To[m * 4 + n];
        }
    }
}

// ---------------- launch ----------------
extern "C" void kernel_launch(void* const* d_in, const int* in_sizes, int n_in,
                              void* d_out, int out_size)
{
    const float* src   = (const float*)d_in[0];
    const float* ref   = (const float*)d_in[1];
    const float* beta  = (const float*)d_in[2];
    const float* alpha = (const float*)d_in[3];
    const int*   nreg  = (n_in > 4) ? (const int*)d_in[4] : nullptr;
    const int*   nsk   = (n_in > 5) ? (const int*)d_in[5] : nullptr;

    float* out = (float*)d_out;
    const long permN = (long)BB * NPT * NPT;
    long off = (long)out_size - permN;
    if (off < 0) off = 0;
    float* perm_out = out + off;
    float* T_out = (off >= BB * 12) ? out : nullptr;

    k_init<<<64, 256>>>(ref);
    const int RMAX = 3, SMAX = 5;
    dim3 gridMat(NPT / 32, BB);     // 512 blocks
    dim3 gridCol(64, BB);           // 16 k-chunks x 4 j-chunks = 1024 blocks
    dim3 gridRow(NPT / 8, BB);      // 2048 blocks
    for (int r = 0; r < RMAX; r++) {
        k_prep<<<64, 256>>>(nreg, r, src);
        k_mat<<<gridMat, 256>>>(nreg, r, beta, alpha);        // writes fp16 E + row pass s=0 (ev==1)
        for (int s = 0; s < SMAX; s++) {
            k_colp<<<gridCol, 256>>>(nreg, nsk, r, s);
            if (s < SMAX - 1)
                k_rowp<<<gridRow, 256>>>(nreg, nsk, r, s + 1);
        }
        k_consume<<<gridMat, 256>>>(nreg, r, beta, alpha, perm_out);
        k_fit<<<BB, 256>>>(nreg, r, T_out);
    }
}

// round 9
// speedup vs baseline: 1.4963x; 1.1034x over previous
#include <cuda_runtime.h>
#include <cuda_fp16.h>
#include <math.h>

#define BB  16
#define NPT 1024
#define EPSW 1e-5f
#define L2E 1.4426950408889634f

typedef unsigned long long ull;

// ---------------- scratch (static device globals; no allocations) ----------------
static __device__ __half g_Eh[BB][NPT][NPT];     // exp(affinity) fp16, 32MB, L2-resident
static __device__ float  g_part[4][BB][NPT];     // column-pass partial sums (4 j-chunks)
static __device__ float  g_refSoA[BB][6][NPT];   // ref features, SoA
static __device__ float  g_gn[BB][NPT];          // |g_k|^2
static __device__ float  g_featS[BB][6][NPT];    // transformed src features, SoA
static __device__ float  g_fn[BB][NPT];          // |f_j|^2
static __device__ float  g_eu[BB][NPT];          // exp(-u_j)
static __device__ float  g_w[BB][NPT];           // row weights (sum_k perm)
static __device__ float  g_wrx[BB][NPT];
static __device__ float  g_wry[BB][NPT];
static __device__ float  g_wrz[BB][NPT];
static __device__ double g_T[BB][12];            // accumulated transform, row-major 3x4

__device__ __forceinline__ float fast_ex2(float x){ float y; asm("ex2.approx.ftz.f32 %0, %1;" : "=f"(y) : "f"(x)); return y; }
__device__ __forceinline__ int dval(const int* p, int d){ return p ? __ldg(p) : d; }

// packed f32x2 helpers (Blackwell FFMA2)
__device__ __forceinline__ ull pack2(float lo, float hi){ ull r; asm("mov.b64 %0, {%1, %2};" : "=l"(r) : "f"(lo), "f"(hi)); return r; }
__device__ __forceinline__ void unpack2(ull v, float& lo, float& hi){ asm("mov.b64 {%0, %1}, %2;" : "=f"(lo), "=f"(hi) : "l"(v)); }
__device__ __forceinline__ ull fma2(ull a, ull b, ull c){ ull d; asm("fma.rn.f32x2 %0, %1, %2, %3;" : "=l"(d) : "l"(a), "l"(b), "l"(c)); return d; }
__device__ __forceinline__ ull add2(ull a, ull b){ ull d; asm("add.rn.f32x2 %0, %1, %2;" : "=l"(d) : "l"(a), "l"(b)); return d; }

// ---------------- init: ref -> SoA, |g|^2, transform = I ----------------
__global__ void k_init(const float* __restrict__ ref)
{
    int idx = blockIdx.x * 256 + threadIdx.x;
    if (idx < BB * NPT) {
        int b = idx >> 10, k = idx & 1023;
        const float* p = ref + (size_t)idx * 6;
        float n = 0.f;
#pragma unroll
        for (int c = 0; c < 6; c++) { float x = p[c]; g_refSoA[b][c][k] = x; n += x * x; }
        g_gn[b][k] = n;
    }
    if (idx < BB) {
        double* T = g_T[idx];
#pragma unroll
        for (int m = 0; m < 3; m++)
#pragma unroll
            for (int c = 0; c < 4; c++) T[m * 4 + c] = (m == c) ? 1.0 : 0.0;
    }
}

// ---------------- prep: src_t = R*src + t, features SoA ----------------
__global__ void k_prep(const int* nreg, int r, const float* __restrict__ src)
{
    if (r >= dval(nreg, 3)) return;
    int idx = blockIdx.x * 256 + threadIdx.x;
    if (idx >= BB * NPT) return;
    int b = idx >> 10, j = idx & 1023;
    const double* T = g_T[b];
    const float* p = src + (size_t)idx * 6;
    float x = p[0], y = p[1], z = p[2], n3 = p[3], n4 = p[4], n5 = p[5];
    float q0 = (float)(T[0] * x + T[1] * y + T[2]  * z + T[3]);
    float q1 = (float)(T[4] * x + T[5] * y + T[6]  * z + T[7]);
    float q2 = (float)(T[8] * x + T[9] * y + T[10] * z + T[11]);
    g_featS[b][0][j] = q0; g_featS[b][1][j] = q1; g_featS[b][2][j] = q2;
    g_featS[b][3][j] = n3; g_featS[b][4][j] = n4; g_featS[b][5][j] = n5;
    g_fn[b][j] = q0*q0 + q1*q1 + q2*q2 + n3*n3 + n4*n4 + n5*n5;
}

// ---------------- mat: E = exp(a) (fp16) via f32x2, fused first row pass (ev==1) ----------------
__global__ void __launch_bounds__(256) k_mat(const int* nreg, int r,
                                             const float* __restrict__ beta_, const float* __restrict__ alpha_)
{
    if (r >= dval(nreg, 3)) return;
    int b = blockIdx.y;
    __shared__ float gs[6][NPT];
    __shared__ float pk[NPT];
    float bl = beta_[b] * L2E;
    for (int i = threadIdx.x; i < NPT; i += 256) {
#pragma unroll
        for (int c = 0; c < 6; c++) gs[c][i] = g_refSoA[b][c][i];
        pk[i] = bl * g_gn[b][i];
    }
    __syncthreads();
    int warp = threadIdx.x >> 5, lane = threadIdx.x & 31;
    int j0 = blockIdx.x * 32 + warp * 4;
    float al = alpha_[b];
    ull wj2[4][6], cj2[4];
#pragma unroll
    for (int t = 0; t < 4; t++) {
        int j = j0 + t;
#pragma unroll
        for (int c = 0; c < 6; c++) { float w = 2.f * bl * g_featS[b][c][j]; wj2[t][c] = pack2(w, w); }
        float cj = bl * (al - g_fn[b][j]);
        cj2[t] = pack2(cj, cj);
    }
    __half2* E0 = (__half2*)&g_Eh[b][j0][0];
    float acc[4] = {0.f, 0.f, 0.f, 0.f};
#pragma unroll 2
    for (int i = 0; i < 16; i++) {
        int kk = i * 32 + lane;                       // pair index: k = 2*kk, 2*kk+1
        ull g2[6];
#pragma unroll
        for (int c = 0; c < 6; c++) {
            float2 G = ((const float2*)&gs[c][0])[kk];
            g2[c] = pack2(G.x, G.y);
        }
        float2 P = ((const float2*)pk)[kk];
        ull pn = pack2(-P.x, -P.y);
#pragma unroll
        for (int t = 0; t < 4; t++) {
            ull a = add2(cj2[t], pn);
#pragma unroll
            for (int c = 0; c < 6; c++) a = fma2(wj2[t][c], g2[c], a);
            float ax, ay; unpack2(a, ax, ay);
            float e0 = fast_ex2(ax), e1 = fast_ex2(ay);
            E0[t * (NPT / 2) + kk] = __floats2half2_rn(e0, e1);
            acc[t] += e0 + e1;
        }
    }
#pragma unroll
    for (int t = 0; t < 4; t++)
#pragma unroll
        for (int o = 16; o; o >>= 1) acc[t] += __shfl_xor_sync(0xffffffffu, acc[t], o);
    if (lane == 0) {
#pragma unroll
        for (int t = 0; t < 4; t++) g_eu[b][j0 + t] = 1.f / (1.f + acc[t]);
    }
}

// ---------------- col pass (partial): part[jc][b][k] = sum_{j in chunk} E_jk * eu_j ----------------
// grid (32, BB): kc = x&7 (8 chunks of 128 cols), jc = x>>3 (4 chunks of 256 rows)
__global__ void __launch_bounds__(256) k_colp(const int* nreg, const int* nsk, int r, int s)
{
    if (r >= dval(nreg, 3) || s >= dval(nsk, 5)) return;
    int b  = blockIdx.y;
    int kc = blockIdx.x & 7;
    int jc = blockIdx.x >> 3;
    int t = threadIdx.x;
    int col8 = t & 15;          // 16 groups of 8 columns
    int rg   = t >> 4;          // 16 row-chunks of 16 rows
    __shared__ float eus[256];
    __shared__ float red[16][128];
    eus[t] = g_eu[b][jc * 256 + t];
    __syncthreads();
    const uint4* Ebase = (const uint4*)(&g_Eh[b][jc * 256 + rg * 16][kc * 128 + col8 * 8]);
    const int rowStride = NPT / 8;   // uint4 elements per row
    float a0=0,a1=0,a2=0,a3=0,a4=0,a5=0,a6=0,a7=0;
#pragma unroll
    for (int jj = 0; jj < 16; jj++) {
        uint4 v = Ebase[jj * rowStride];
        float e = eus[rg * 16 + jj];
        float2 p0 = __half22float2(*(const __half2*)&v.x);
        float2 p1 = __half22float2(*(const __half2*)&v.y);
        float2 p2 = __half22float2(*(const __half2*)&v.z);
        float2 p3 = __half22float2(*(const __half2*)&v.w);
        a0 = fmaf(p0.x, e, a0); a1 = fmaf(p0.y, e, a1);
        a2 = fmaf(p1.x, e, a2); a3 = fmaf(p1.y, e, a3);
        a4 = fmaf(p2.x, e, a4); a5 = fmaf(p2.y, e, a5);
        a6 = fmaf(p3.x, e, a6); a7 = fmaf(p3.y, e, a7);
    }
    // store partials: element cidx of this thread -> red[rg][cidx*16 + col8]
    red[rg][0*16 + col8] = a0; red[rg][1*16 + col8] = a1;
    red[rg][2*16 + col8] = a2; red[rg][3*16 + col8] = a3;
    red[rg][4*16 + col8] = a4; red[rg][5*16 + col8] = a5;
    red[rg][6*16 + col8] = a6; red[rg][7*16 + col8] = a7;
    __syncthreads();
    if (t < 128) {
        int c8 = t >> 3, ci = t & 7;       // column c = c8*8 + ci
        float s4 = 0.f;
#pragma unroll
        for (int rr = 0; rr < 16; rr++) s4 += red[rr][ci * 16 + c8];
        g_part[jc][b][kc * 128 + c8 * 8 + ci] = s4;
    }
}

// ---------------- row pass: eu_j = 1/(1 + sum_k E_jk * ev_k), ev folded from partials ----------------
// grid (32, BB): 8 warps/block, 4 rows/warp
__global__ void __launch_bounds__(256) k_rowp(const int* nreg, const int* nsk, int r, int s)
{
    if (r >= dval(nreg, 3) || s >= dval(nsk, 5)) return;
    int b = blockIdx.y;
    __shared__ float evs[NPT];
    for (int i = threadIdx.x; i < NPT; i += 256)
        evs[i] = 1.f / (1.f + g_part[0][b][i] + g_part[1][b][i] + g_part[2][b][i] + g_part[3][b][i]);
    __syncthreads();
    int w = threadIdx.x >> 5, lane = threadIdx.x & 31;
    int j0 = (blockIdx.x * 8 + w) * 4;
    float acc0 = 0.f, acc1 = 0.f, acc2 = 0.f, acc3 = 0.f;
#pragma unroll
    for (int i = 0; i < 4; i++) {
        int k0 = i * 256 + lane * 8;
        float2 e0 = *(const float2*)&evs[k0];
        float2 e1 = *(const float2*)&evs[k0 + 2];
        float2 e2 = *(const float2*)&evs[k0 + 4];
        float2 e3 = *(const float2*)&evs[k0 + 6];
        uint4 v0 = *(const uint4*)(&g_Eh[b][j0 + 0][k0]);
        uint4 v1 = *(const uint4*)(&g_Eh[b][j0 + 1][k0]);
        uint4 v2 = *(const uint4*)(&g_Eh[b][j0 + 2][k0]);
        uint4 v3 = *(const uint4*)(&g_Eh[b][j0 + 3][k0]);
        {
            float2 p0 = __half22float2(*(const __half2*)&v0.x), p1 = __half22float2(*(const __half2*)&v0.y);
            float2 p2 = __half22float2(*(const __half2*)&v0.z), p3 = __half22float2(*(const __half2*)&v0.w);
            acc0 = fmaf(p0.x, e0.x, fmaf(p0.y, e0.y, acc0));
            acc0 = fmaf(p1.x, e1.x, fmaf(p1.y, e1.y, acc0));
            acc0 = fmaf(p2.x, e2.x, fmaf(p2.y, e2.y, acc0));
            acc0 = fmaf(p3.x, e3.x, fmaf(p3.y, e3.y, acc0));
        }
        {
            float2 p0 = __half22float2(*(const __half2*)&v1.x), p1 = __half22float2(*(const __half2*)&v1.y);
            float2 p2 = __half22float2(*(const __half2*)&v1.z), p3 = __half22float2(*(const __half2*)&v1.w);
            acc1 = fmaf(p0.x, e0.x, fmaf(p0.y, e0.y, acc1));
            acc1 = fmaf(p1.x, e1.x, fmaf(p1.y, e1.y, acc1));
            acc1 = fmaf(p2.x, e2.x, fmaf(p2.y, e2.y, acc1));
            acc1 = fmaf(p3.x, e3.x, fmaf(p3.y, e3.y, acc1));
        }
        {
            float2 p0 = __half22float2(*(const __half2*)&v2.x), p1 = __half22float2(*(const __half2*)&v2.y);
            float2 p2 = __half22float2(*(const __half2*)&v2.z), p3 = __half22float2(*(const __half2*)&v2.w);
            acc2 = fmaf(p0.x, e0.x, fmaf(p0.y, e0.y, acc2));
            acc2 = fmaf(p1.x, e1.x, fmaf(p1.y, e1.y, acc2));
            acc2 = fmaf(p2.x, e2.x, fmaf(p2.y, e2.y, acc2));
            acc2 = fmaf(p3.x, e3.x, fmaf(p3.y, e3.y, acc2));
        }
        {
            float2 p0 = __half22float2(*(const __half2*)&v3.x), p1 = __half22float2(*(const __half2*)&v3.y);
            float2 p2 = __half22float2(*(const __half2*)&v3.z), p3 = __half22float2(*(const __half2*)&v3.w);
            acc3 = fmaf(p0.x, e0.x, fmaf(p0.y, e0.y, acc3));
            acc3 = fmaf(p1.x, e1.x, fmaf(p1.y, e1.y, acc3));
            acc3 = fmaf(p2.x, e2.x, fmaf(p2.y, e2.y, acc3));
            acc3 = fmaf(p3.x, e3.x, fmaf(p3.y, e3.y, acc3));
        }
    }
#pragma unroll
    for (int o = 16; o; o >>= 1) {
        acc0 += __shfl_xor_sync(0xffffffffu, acc0, o);
        acc1 += __shfl_xor_sync(0xffffffffu, acc1, o);
        acc2 += __shfl_xor_sync(0xffffffffu, acc2, o);
        acc3 += __shfl_xor_sync(0xffffffffu, acc3, o);
    }
    if (lane == 0) {
        g_eu[b][j0 + 0] = 1.f / (1.f + acc0);
        g_eu[b][j0 + 1] = 1.f / (1.f + acc1);
        g_eu[b][j0 + 2] = 1.f / (1.f + acc2);
        g_eu[b][j0 + 3] = 1.f / (1.f + acc3);
    }
}

// ---------------- consume: exact fp32 recompute of E; row sums, perm @ ref_xyz, perm write ----------------
__global__ void __launch_bounds__(256) k_consume(const int* nreg, int r,
                                                 const float* __restrict__ beta_, const float* __restrict__ alpha_,
                                                 float* __restrict__ perm_out)
{
    int nr = dval(nreg, 3);
    if (r >= nr) return;
    bool last = (r == nr - 1);
    int b = blockIdx.y;
    __shared__ float gs[6][NPT];
    __shared__ float pk[NPT];
    __shared__ float evs[NPT];
    float bl = beta_[b] * L2E;
    for (int i = threadIdx.x; i < NPT; i += 256) {
#pragma unroll
        for (int c = 0; c < 6; c++) gs[c][i] = g_refSoA[b][c][i];
        pk[i] = bl * g_gn[b][i];
        evs[i] = 1.f / (1.f + g_part[0][b][i] + g_part[1][b][i] + g_part[2][b][i] + g_part[3][b][i]);
    }
    __syncthreads();
    int warp = threadIdx.x >> 5, lane = threadIdx.x & 31;
    int j0 = blockIdx.x * 32 + warp * 4;
    float al = alpha_[b];
    float wj[4][6], cj[4], eu[4];
#pragma unroll
    for (int t = 0; t < 4; t++) {
        int j = j0 + t;
#pragma unroll
        for (int c = 0; c < 6; c++) wj[t][c] = 2.f * bl * g_featS[b][c][j];
        cj[t] = bl * (al - g_fn[b][j]);
        eu[t] = g_eu[b][j];
    }
    float S[4] = {0,0,0,0}, SX[4] = {0,0,0,0}, SY[4] = {0,0,0,0}, SZ[4] = {0,0,0,0};
    if (last) {
        float* pb[4];
#pragma unroll
        for (int t = 0; t < 4; t++) pb[t] = perm_out + ((size_t)(b * NPT + j0 + t)) * NPT;
#pragma unroll 2
        for (int i = 0; i < 32; i++) {
            int k = i * 32 + lane;
            float G[6];
#pragma unroll
            for (int c = 0; c < 6; c++) G[c] = gs[c][k];
            float P = pk[k], ev = evs[k];
#pragma unroll
            for (int t = 0; t < 4; t++) {
                float a = cj[t] - P;
#pragma unroll
                for (int c = 0; c < 6; c++) a = fmaf(wj[t][c], G[c], a);
                float e = fast_ex2(a) * ev;
                S[t] += e;
                SX[t] = fmaf(e, G[0], SX[t]);
                SY[t] = fmaf(e, G[1], SY[t]);
                SZ[t] = fmaf(e, G[2], SZ[t]);
                pb[t][k] = e * eu[t];
            }
        }
    } else {
#pragma unroll 2
        for (int i = 0; i < 32; i++) {
            int k = i * 32 + lane;
            float G[6];
#pragma unroll
            for (int c = 0; c < 6; c++) G[c] = gs[c][k];
            float P = pk[k], ev = evs[k];
#pragma unroll
            for (int t = 0; t < 4; t++) {
                float a = cj[t] - P;
#pragma unroll
                for (int c = 0; c < 6; c++) a = fmaf(wj[t][c], G[c], a);
                float e = fast_ex2(a) * ev;
                S[t] += e;
                SX[t] = fmaf(e, G[0], SX[t]);
                SY[t] = fmaf(e, G[1], SY[t]);
                SZ[t] = fmaf(e, G[2], SZ[t]);
            }
        }
    }
#pragma unroll
    for (int t = 0; t < 4; t++) {
#pragma unroll
        for (int o = 16; o; o >>= 1) {
            S[t]  += __shfl_xor_sync(0xffffffffu, S[t],  o);
            SX[t] += __shfl_xor_sync(0xffffffffu, SX[t], o);
            SY[t] += __shfl_xor_sync(0xffffffffu, SY[t], o);
            SZ[t] += __shfl_xor_sync(0xffffffffu, SZ[t], o);
        }
    }
    if (lane == 0) {
#pragma unroll
        for (int t = 0; t < 4; t++) {
            int j = j0 + t;
            float W = S[t] * eu[t];
            g_w[b][j] = W;
            float inv = 1.f / (W + EPSW);
            g_wrx[b][j] = SX[t] * eu[t] * inv;
            g_wry[b][j] = SY[t] * eu[t] * inv;
            g_wrz[b][j] = SZ[t] * eu[t] * inv;
        }
    }
}

// ---------------- fit: weighted Kabsch (fp64 Jacobi SVD) + compose transform ----------------
__global__ void __launch_bounds__(256) k_fit(const int* nreg, int r, float* __restrict__ T_out)
{
    int nr = dval(nreg, 3);
    if (r >= nr) return;
    int b = blockIdx.x;
    int lane = threadIdx.x & 31, warp = threadIdx.x >> 5;
    __shared__ double sred[8][9];
    __shared__ double sc[8];

    double acc[7] = {0,0,0,0,0,0,0};
    for (int j = threadIdx.x; j < NPT; j += 256) {
        double w  = g_w[b][j];
        double ax = g_featS[b][0][j], ay = g_featS[b][1][j], az = g_featS[b][2][j];
        double bx = g_wrx[b][j], by = g_wry[b][j], bz = g_wrz[b][j];
        acc[0] += w;
        acc[1] += w*ax; acc[2] += w*ay; acc[3] += w*az;
        acc[4] += w*bx; acc[5] += w*by; acc[6] += w*bz;
    }
#pragma unroll
    for (int i = 0; i < 7; i++)
#pragma unroll
        for (int o = 16; o; o >>= 1) acc[i] += __shfl_xor_sync(0xffffffffu, acc[i], o);
    if (lane == 0)
#pragma unroll
        for (int i = 0; i < 7; i++) sred[warp][i] = acc[i];
    __syncthreads();
    if (threadIdx.x == 0) {
        double tot[7] = {0,0,0,0,0,0,0};
        for (int w = 0; w < 8; w++)
            for (int i = 0; i < 7; i++) tot[i] += sred[w][i];
        double den = tot[0] + 1e-5;
        sc[0] = den;
        for (int i = 0; i < 6; i++) sc[1 + i] = tot[1 + i] / den;
    }
    __syncthreads();
    double den = sc[0];
    double ca0 = sc[1], ca1 = sc[2], ca2 = sc[3];
    double cb0 = sc[4], cb1 = sc[5], cb2 = sc[6];

    double cv[9] = {0,0,0,0,0,0,0,0,0};
    for (int j = threadIdx.x; j < NPT; j += 256) {
        double wn = (double)g_w[b][j] / den;
        double ax = g_featS[b][0][j] - ca0, ay = g_featS[b][1][j] - ca1, az = g_featS[b][2][j] - ca2;
        double bx = g_wrx[b][j] - cb0, by = g_wry[b][j] - cb1, bz = g_wrz[b][j] - cb2;
        cv[0] += wn*ax*bx; cv[1] += wn*ax*by; cv[2] += wn*ax*bz;
        cv[3] += wn*ay*bx; cv[4] += wn*ay*by; cv[5] += wn*ay*bz;
        cv[6] += wn*az*bx; cv[7] += wn*az*by; cv[8] += wn*az*bz;
    }
#pragma unroll
    for (int i = 0; i < 9; i++)
#pragma unroll
        for (int o = 16; o; o >>= 1) cv[i] += __shfl_xor_sync(0xffffffffu, cv[i], o);
    if (lane == 0)
#pragma unroll
        for (int i = 0; i < 9; i++) sred[warp][i] = cv[i];
    __syncthreads();

    if (threadIdx.x == 0) {
        double C[3][3];
        {
            double tot[9] = {0,0,0,0,0,0,0,0,0};
            for (int w = 0; w < 8; w++)
                for (int i = 0; i < 9; i++) tot[i] += sred[w][i];
            for (int m = 0; m < 3; m++)
                for (int n = 0; n < 3; n++) C[m][n] = tot[m * 3 + n];
        }
        double A[3][3];
        for (int i = 0; i < 3; i++)
            for (int j = 0; j < 3; j++)
                A[i][j] = C[0][i]*C[0][j] + C[1][i]*C[1][j] + C[2][i]*C[2][j];
        double V[3][3] = {{1,0,0},{0,1,0},{0,0,1}};
        const int PP[3] = {0,0,1}, QQ[3] = {1,2,2};
        for (int sweep = 0; sweep < 30; sweep++) {
            double off = A[0][1]*A[0][1] + A[0][2]*A[0][2] + A[1][2]*A[1][2];
            if (off < 1e-26) break;
            for (int pi = 0; pi < 3; pi++) {
                int p = PP[pi], q = QQ[pi];
                double apq = A[p][q];
                if (fabs(apq) < 1e-300) continue;
                double theta = (A[q][q] - A[p][p]) / (2.0 * apq);
                double tt = ((theta >= 0.0) ? 1.0 : -1.0) / (fabs(theta) + sqrt(theta*theta + 1.0));
                double c = 1.0 / sqrt(tt*tt + 1.0), sn = tt * c;
                int m = 3 - p - q;
                double amp = A[m][p], amq = A[m][q];
                double app = A[p][p], aqq = A[q][q];
                A[p][p] = app - tt * apq;
                A[q][q] = aqq + tt * apq;
                A[p][q] = A[q][p] = 0.0;
                A[m][p] = A[p][m] = c*amp - sn*amq;
                A[m][q] = A[q][m] = sn*amp + c*amq;
                for (int mm = 0; mm < 3; mm++) {
                    double vp = V[mm][p], vq = V[mm][q];
                    V[mm][p] = c*vp - sn*vq;
                    V[mm][q] = sn*vp + c*vq;
                }
            }
        }
        double lam[3] = {A[0][0], A[1][1], A[2][2]};
        for (int i = 0; i < 2; i++)
            for (int j = i + 1; j < 3; j++)
                if (lam[j] > lam[i]) {
                    double tl = lam[i]; lam[i] = lam[j]; lam[j] = tl;
                    for (int m = 0; m < 3; m++) { double tv = V[m][i]; V[m][i] = V[m][j]; V[m][j] = tv; }
                }
        double v0[3] = {V[0][0], V[1][0], V[2][0]};
        double v1[3] = {V[0][1], V[1][1], V[2][1]};
        double v2[3] = {V[0][2], V[1][2], V[2][2]};
        double u0[3], u1[3], u2[3];
        for (int m = 0; m < 3; m++) {
            u0[m] = C[m][0]*v0[0] + C[m][1]*v0[1] + C[m][2]*v0[2];
            u1[m] = C[m][0]*v1[0] + C[m][1]*v1[1] + C[m][2]*v1[2];
            u2[m] = C[m][0]*v2[0] + C[m][1]*v2[1] + C[m][2]*v2[2];
        }
        double n0 = sqrt(u0[0]*u0[0] + u0[1]*u0[1] + u0[2]*u0[2]);
        if (n0 > 1e-150) { u0[0] /= n0; u0[1] /= n0; u0[2] /= n0; }
        else { u0[0] = 1; u0[1] = 0; u0[2] = 0; n0 = 0; }
        double d01 = u0[0]*u1[0] + u0[1]*u1[1] + u0[2]*u1[2];
        for (int m = 0; m < 3; m++) u1[m] -= d01 * u0[m];
        double n1 = sqrt(u1[0]*u1[0] + u1[1]*u1[1] + u1[2]*u1[2]);
        if (n1 > 1e-150) { u1[0] /= n1; u1[1] /= n1; u1[2] /= n1; }
        else {
            double e[3] = {0,0,0};
            e[(fabs(u0[0]) < 0.9) ? 0 : 1] = 1.0;
            double de = u0[0]*e[0] + u0[1]*e[1] + u0[2]*e[2];
            for (int m = 0; m < 3; m++) u1[m] = e[m] - de * u0[m];
            double nn = sqrt(u1[0]*u1[0] + u1[1]*u1[1] + u1[2]*u1[2]);
            for (int m = 0; m < 3; m++) u1[m] /= nn;
        }
        double d02 = u0[0]*u2[0] + u0[1]*u2[1] + u0[2]*u2[2];
        double d12 = u1[0]*u2[0] + u1[1]*u2[1] + u1[2]*u2[2];
        for (int m = 0; m < 3; m++) u2[m] -= d02 * u0[m] + d12 * u1[m];
        double n2 = sqrt(u2[0]*u2[0] + u2[1]*u2[1] + u2[2]*u2[2]);
        if (n2 > 1e-12 * (n0 + 1e-300)) { u2[0] /= n2; u2[1] /= n2; u2[2] /= n2; }
        else {
            u2[0] = u0[1]*u1[2] - u0[2]*u1[1];
            u2[1] = u0[2]*u1[0] - u0[0]*u1[2];
            u2[2] = u0[0]*u1[1] - u0[1]*u1[0];
        }
        double cx0 = u1[1]*u2[2] - u1[2]*u2[1];
        double cx1 = u1[2]*u2[0] - u1[0]*u2[2];
        double cx2 = u1[0]*u2[1] - u1[1]*u2[0];
        double detU = u0[0]*cx0 + u0[1]*cx1 + u0[2]*cx2;
        double cy0 = v1[1]*v2[2] - v1[2]*v2[1];
        double cy1 = v1[2]*v2[0] - v1[0]*v2[2];
        double cy2 = v1[0]*v2[1] - v1[1]*v2[0];
        double detV = v0[0]*cy0 + v0[1]*cy1 + v0[2]*cy2;
        double dd = (detU * detV >= 0.0) ? 1.0 : -1.0;
        double R[3][3];
        for (int m = 0; m < 3; m++)
            for (int n = 0; n < 3; n++)
                R[m][n] = v0[m]*u0[n] + v1[m]*u1[n] + dd * v2[m]*u2[n];
        double t3[3];
        t3[0] = cb0 - (R[0][0]*ca0 + R[0][1]*ca1 + R[0][2]*ca2);
        t3[1] = cb1 - (R[1][0]*ca0 + R[1][1]*ca1 + R[1][2]*ca2);
        t3[2] = cb2 - (R[2][0]*ca0 + R[2][1]*ca1 + R[2][2]*ca2);
        double* To = g_T[b];
        double Rn[9], tn[3];
        for (int m = 0; m < 3; m++) {
            for (int n = 0; n < 3; n++)
                Rn[m*3+n] = R[m][0]*To[0*4+n] + R[m][1]*To[1*4+n] + R[m][2]*To[2*4+n];
            tn[m] = R[m][0]*To[3] + R[m][1]*To[7] + R[m][2]*To[11] + t3[m];
        }
        for (int m = 0; m < 3; m++) {
            for (int n = 0; n < 3; n++) To[m*4+n] = Rn[m*3+n];
            To[m*4+3] = tn[m];
        }
        if (r == nr - 1 && T_out) {
            for (int m = 0; m < 3; m++)
                for (int n = 0; n < 4; n++)
                    T_out[b * 12 + m * 4 + n] = (float)To[m * 4 + n];
        }
    }
}

// ---------------- launch ----------------
extern "C" void kernel_launch(void* const* d_in, const int* in_sizes, int n_in,
                              void* d_out, int out_size)
{
    const float* src   = (const float*)d_in[0];
    const float* ref   = (const float*)d_in[1];
    const float* beta  = (const float*)d_in[2];
    const float* alpha = (const float*)d_in[3];
    const int*   nreg  = (n_in > 4) ? (const int*)d_in[4] : nullptr;
    const int*   nsk   = (n_in > 5) ? (const int*)d_in[5] : nullptr;

    float* out = (float*)d_out;
    const long permN = (long)BB * NPT * NPT;
    long off = (long)out_size - permN;
    if (off < 0) off = 0;
    float* perm_out = out + off;
    float* T_out = (off >= BB * 12) ? out : nullptr;

    k_init<<<64, 256>>>(ref);
    const int RMAX = 3, SMAX = 5;
    dim3 gridMat(NPT / 32, BB);     // 512 blocks
    dim3 gridCol(32, BB);           // 8 k-chunks x 4 j-chunks = 512 blocks
    dim3 gridRow(32, BB);           // 8 warps x 4 rows = 32 rows/block
    for (int r = 0; r < RMAX; r++) {
        k_prep<<<64, 256>>>(nreg, r, src);
        k_mat<<<gridMat, 256>>>(nreg, r, beta, alpha);        // writes fp16 E + row pass s=0 (ev==1)
        for (int s = 0; s < SMAX; s++) {
            k_colp<<<gridCol, 256>>>(nreg, nsk, r, s);
            if (s < SMAX - 1)
                k_rowp<<<gridRow, 256>>>(nreg, nsk, r, s + 1);
        }
        k_consume<<<gridMat, 256>>>(nreg, r, beta, alpha, perm_out);
        k_fit<<<BB, 256>>>(nreg, r, T_out);
    }
}